// round 13
// baseline (speedup 1.0000x reference)
#include <cuda_runtime.h>

#define LRES 1024
#define TOPK 48
#define EF   416
#define SF   1280

#define OFF_E       0ull
#define OFF_EIDX    6291456ull
#define OFF_ES      6340608ull
#define OFF_EIDXSUB 12632064ull

__device__ float g_coords[LRES * 15];
__device__ int   g_eidx[LRES * TOPK];
__device__ float g_dnb[LRES * TOPK];
__device__ float g_wsr[128 * SF];   // tf32-rounded W_s
__device__ float g_wer[128 * EF];   // tf32-rounded W_e

__device__ __forceinline__ unsigned long long u64min_(unsigned long long a,
                                                      unsigned long long b) {
    return a < b ? a : b;
}

__device__ __forceinline__ void cp_commit() {
    asm volatile("cp.async.commit_group;" ::: "memory");
}
__device__ __forceinline__ void cp_wait0() {
    asm volatile("cp.async.wait_group 0;" ::: "memory");
}

__device__ __forceinline__ unsigned cvt_tf32(float x) {
    unsigned u;
    asm("cvt.rna.tf32.f32 %0, %1;" : "=r"(u) : "f"(x));
    return u;
}
__device__ __forceinline__ float tf32f(float x) {
    return __uint_as_float(cvt_tf32(x));
}

__device__ __forceinline__ void mma_tf32(float& d0, float& d1, float& d2,
                                         float& d3, unsigned a0, unsigned a1,
                                         unsigned a2, unsigned a3, unsigned b0,
                                         unsigned b1) {
    asm volatile(
        "mma.sync.aligned.m16n8k8.row.col.f32.tf32.tf32.f32 "
        "{%0,%1,%2,%3}, {%4,%5,%6,%7}, {%8,%9}, {%0,%1,%2,%3};"
        : "+f"(d0), "+f"(d1), "+f"(d2), "+f"(d3)
        : "r"(a0), "r"(a1), "r"(a2), "r"(a3), "r"(b0), "r"(b1));
}

// Chained RBF; ROUND -> store tf32-rounded values.
template <int NB, bool ROUND>
__device__ __forceinline__ void rbf_gen(float D, float m, float* __restrict__ fr,
                                        float SINV, float D2, float E2c) {
    float s = (D - 2.0f) * SINV;
    float v = __expf(-D2 * s * s);
    float g = __expf(D2 * (2.0f * s - 1.0f));
    float vals[NB];
    vals[0] = v;
    #pragma unroll
    for (int r = 1; r < NB; r++) { v *= g; g *= E2c; vals[r] = v; }
    if (vals[0] < 1e-30f) {
        float sN = s - (float)(NB - 1);
        float v1 = __expf(-D2 * sN * sN);
        float g1 = __expf(-D2 * (2.0f * sN + 1.0f));
        vals[NB - 1] = fmaxf(vals[NB - 1], v1);
        #pragma unroll
        for (int r = NB - 2; r >= 0; r--) {
            v1 *= g1; g1 *= E2c;
            vals[r] = fmaxf(vals[r], v1);
        }
    }
    #pragma unroll
    for (int r = 0; r < NB; r++)
        fr[r] = ROUND ? tf32f(m * vals[r]) : m * vals[r];
}

#define E_SINV 0.75f
#define E_D2   1.13777778f
#define E_E2   0.10273980f
#define S_SINV 0.35f
#define S_D2   1.30612245f
#define S_E2   0.07336966f

// stage 128ch x 32feat fp32 tile -> Wsm[ch*36 + f], 16B cp.async
__device__ __forceinline__ void stage_ws_async(const float* __restrict__ Wsrc,
                                               int stride, int st,
                                               float* __restrict__ Wsm,
                                               int tid) {
    #pragma unroll
    for (int p = tid; p < 1024; p += 256) {
        int ch = p >> 3, fc = p & 7;
        const float* src = Wsrc + ch * stride + st * 32 + fc * 4;
        unsigned int dst =
            (unsigned int)__cvta_generic_to_shared(Wsm + ch * 36 + fc * 4);
        asm volatile("cp.async.ca.shared.global [%0], [%1], 16;"
                     :: "r"(dst), "l"(src) : "memory");
    }
}

// ---------------------------------------------------------------------------
__global__ void wcvt_kernel(const float* __restrict__ Ws,
                            const float* __restrict__ We) {
    int i = blockIdx.x * 256 + threadIdx.x;
    if (i < 128 * SF) g_wsr[i] = tf32f(Ws[i]);
    if (i < 128 * EF) g_wer[i] = tf32f(We[i]);
}

// ---------------------------------------------------------------------------
__global__ void geom_kernel(const float* __restrict__ X) {
    int i = blockIdx.x * blockDim.x + threadIdx.x;
    if (i >= LRES) return;
    const float* xi = X + (size_t)i * 37 * 3;
    float n0 = xi[0],  n1 = xi[1],  n2 = xi[2];
    float a0 = xi[3],  a1 = xi[4],  a2 = xi[5];
    float c0 = xi[6],  c1 = xi[7],  c2 = xi[8];
    float o0 = xi[12], o1 = xi[13], o2 = xi[14];
    float b0 = a0 - n0, b1 = a1 - n1, b2 = a2 - n2;
    float d0 = c0 - a0, d1 = c1 - a1, d2 = c2 - a2;
    float x0 = b1 * d2 - b2 * d1;
    float x1 = b2 * d0 - b0 * d2;
    float x2 = b0 * d1 - b1 * d0;
    float cb0 = -0.58273431f * x0 + 0.56802827f * b0 - 0.54067466f * d0 + a0;
    float cb1 = -0.58273431f * x1 + 0.56802827f * b1 - 0.54067466f * d1 + a1;
    float cb2 = -0.58273431f * x2 + 0.56802827f * b2 - 0.54067466f * d2 + a2;
    float* dst = g_coords + i * 15;
    dst[0] = n0;  dst[1] = n1;  dst[2] = n2;
    dst[3] = a0;  dst[4] = a1;  dst[5] = a2;
    dst[6] = c0;  dst[7] = c1;  dst[8] = c2;
    dst[9] = o0;  dst[10] = o1; dst[11] = o2;
    dst[12] = cb0; dst[13] = cb1; dst[14] = cb2;
}

// ---------------------------------------------------------------------------
__global__ void topk_kernel(const float* __restrict__ X,
                            const float* __restrict__ mask,
                            float* __restrict__ out) {
    __shared__ float dsh[LRES];
    __shared__ unsigned long long keys[LRES];
    __shared__ float wmaxs[8];
    __shared__ unsigned long long wmins[8];
    __shared__ float smDmax;

    int i = blockIdx.x;
    int tid = threadIdx.x;
    float cax = X[((size_t)i * 37 + 1) * 3 + 0];
    float cay = X[((size_t)i * 37 + 1) * 3 + 1];
    float caz = X[((size_t)i * 37 + 1) * 3 + 2];
    float mi = mask[i];

    float lmax = 0.0f;
    for (int j = tid; j < LRES; j += 256) {
        float dx = cax - X[((size_t)j * 37 + 1) * 3 + 0];
        float dy = cay - X[((size_t)j * 37 + 1) * 3 + 1];
        float dz = caz - X[((size_t)j * 37 + 1) * 3 + 2];
        float s = dx * dx + dy * dy + dz * dz;
        float m2 = mi * mask[j];
        float Dv = m2 * sqrtf(s + 1e-6f);
        dsh[j] = Dv;
        lmax = fmaxf(lmax, Dv);
    }
    for (int off = 16; off; off >>= 1)
        lmax = fmaxf(lmax, __shfl_xor_sync(0xffffffffu, lmax, off));
    if ((tid & 31) == 0) wmaxs[tid >> 5] = lmax;
    __syncthreads();
    if (tid == 0) {
        float m = wmaxs[0];
        #pragma unroll
        for (int w = 1; w < 8; w++) m = fmaxf(m, wmaxs[w]);
        smDmax = m;
    }
    __syncthreads();
    float Dmax = smDmax;

    for (int j = tid; j < LRES; j += 256) {
        float m2 = mi * mask[j];
        float Dadj = dsh[j] + (1.0f - m2) * Dmax;
        keys[j] = (((unsigned long long)__float_as_uint(Dadj)) << 32) |
                  (unsigned int)j;
    }
    __syncthreads();

    for (int sel = 0; sel < TOPK; sel++) {
        unsigned long long lmin = 0xffffffffffffffffull;
        #pragma unroll
        for (int c = 0; c < 4; c++) lmin = u64min_(lmin, keys[tid + 256 * c]);
        for (int off = 16; off; off >>= 1) {
            unsigned long long o2 = __shfl_xor_sync(0xffffffffu, lmin, off);
            lmin = u64min_(lmin, o2);
        }
        if ((tid & 31) == 0) wmins[tid >> 5] = lmin;
        __syncthreads();
        if (tid == 0) {
            unsigned long long m = wmins[0];
            #pragma unroll
            for (int w = 1; w < 8; w++) m = u64min_(m, wmins[w]);
            int j = (int)(m & 0xffffffffull);
            float dv = __uint_as_float((unsigned int)(m >> 32));
            g_eidx[i * TOPK + sel] = j;
            g_dnb[i * TOPK + sel] = dv;
            out[OFF_EIDX + (size_t)i * TOPK + sel] = (float)j;
            out[OFF_EIDXSUB + (size_t)i * TOPK + sel] = (float)j;
            keys[j] = 0xffffffffffffffffull;
        }
        __syncthreads();
    }
}

// ---------------------------------------------------------------------------
// LN epilogue for 96 rows (2 residues); row k -> output row 96*bx + k.
__device__ __forceinline__ void ln_epilogue96(const float* __restrict__ h,
                                              const float* __restrict__ gg,
                                              const float* __restrict__ bb,
                                              float* __restrict__ out,
                                              size_t off, int bx, int wid,
                                              int lane) {
    for (int k = wid; k < 96; k += 8) {
        float v0 = h[k * 128 + lane];
        float v1 = h[k * 128 + lane + 32];
        float v2 = h[k * 128 + lane + 64];
        float v3 = h[k * 128 + lane + 96];
        float s = v0 + v1 + v2 + v3;
        for (int o = 16; o; o >>= 1) s += __shfl_xor_sync(0xffffffffu, s, o);
        float mu = s * (1.0f / 128.0f);
        float d0 = v0 - mu, d1 = v1 - mu, d2 = v2 - mu, d3 = v3 - mu;
        float s2 = d0 * d0 + d1 * d1 + d2 * d2 + d3 * d3;
        for (int o = 16; o; o >>= 1) s2 += __shfl_xor_sync(0xffffffffu, s2, o);
        float inv = rsqrtf(s2 * (1.0f / 128.0f) + 1e-5f);
        size_t base = off + ((size_t)(96 * bx + k)) * 128;
        out[base + lane]      = gg[lane]      * d0 * inv + bb[lane];
        out[base + lane + 32] = gg[lane + 32] * d1 * inv + bb[lane + 32];
        out[base + lane + 64] = gg[lane + 64] * d2 * inv + bb[lane + 64];
        out[base + lane + 96] = gg[lane + 96] * d3 * inv + bb[lane + 96];
    }
}

// ---------------------------------------------------------------------------
// Kernel 3: E via tf32 mma, 2 residues/block (M=96). 13 stages of 32 feats.
// smem floats: W0[4608] W1[4608] A0[3456] A1[3456] SD[24*98=2352] = 18480.
// ---------------------------------------------------------------------------
#define E2_W0 0
#define E2_W1 4608
#define E2_A0 9216
#define E2_A1 12672
#define E2_SD 16128
#define E2_TOT 18480

__global__ void __launch_bounds__(256, 2) e_kernel(
    const float* __restrict__ Wpos, const float* __restrict__ bpos,
    const int* __restrict__ ridx, const int* __restrict__ clab,
    const float* __restrict__ ge, const float* __restrict__ be,
    float* __restrict__ out) {
    extern __shared__ float sm[];
    float* SD = sm + E2_SD;
    int bx = blockIdx.x;
    int tid = threadIdx.x;
    int wid = tid >> 5, lane = tid & 31;
    int g = lane >> 2, t = lane & 3;

    stage_ws_async(g_wer, EF, 0, sm + E2_W0, tid);
    cp_commit();

    // stage 0 A-tile: pos16 + rbf16(Dnb) for 96 edges
    if (tid < 96) {
        int e = tid;
        int r = (e >= 48);
        int ires = 2 * bx + r;
        int j = g_eidx[96 * bx + e];
        int offr = ridx[ires] - ridx[j];
        int ec = (clab[ires] == clab[j]) ? 1 : 0;
        int d = min(max(offr + 32, 0), 64) * ec + (1 - ec) * 65;
        float* fr = sm + E2_A0 + e * 36;
        #pragma unroll
        for (int f = 0; f < 16; f++) fr[f] = tf32f(Wpos[f * 66 + d] + bpos[f]);
        rbf_gen<16, true>(g_dnb[96 * bx + e], 1.0f, fr + 16, E_SINV, E_D2,
                          E_E2);
    }

    // seeds: pair distances, 96 edges x 24 pairs
    const signed char pa[24] = {0,2,3,4,1,1,1,1,0,0,0,4,4,3,0,2,3,4,2,3,4,2,3,2};
    const signed char pb[24] = {0,2,3,4,0,2,3,4,2,3,4,2,3,2,1,1,1,1,0,0,0,4,4,3};
    for (int tt = tid; tt < 96 * 24; tt += 256) {
        int k = tt / 24, p = tt - k * 24;
        int r = (k >= 48);
        int ires = 2 * bx + r;
        int j = g_eidx[96 * bx + k];
        const float* A = g_coords + ires * 15 + (int)pa[p] * 3;
        const float* B = g_coords + j * 15 + (int)pb[p] * 3;
        float dx = A[0] - B[0], dy = A[1] - B[1], dz = A[2] - B[2];
        SD[p * 98 + k] = sqrtf(dx * dx + dy * dy + dz * dz + 1e-6f);
    }

    float acc[6][2][4];
    #pragma unroll
    for (int mt = 0; mt < 6; mt++)
        #pragma unroll
        for (int j = 0; j < 2; j++)
            #pragma unroll
            for (int q = 0; q < 4; q++) acc[mt][j][q] = 0.0f;

    for (int st = 0; st < 13; st++) {
        cp_wait0();
        __syncthreads();
        if (st + 1 < 13) {
            stage_ws_async(g_wer, EF, st + 1,
                           sm + (((st + 1) & 1) ? E2_W1 : E2_W0), tid);
            cp_commit();
        }
        const float* Wc = sm + ((st & 1) ? E2_W1 : E2_W0);
        const float* As = sm + ((st & 1) ? E2_A1 : E2_A0);
        #pragma unroll
        for (int k8 = 0; k8 < 4; k8++) {
            int ko = k8 * 8;
            unsigned af[6][4];
            #pragma unroll
            for (int mt = 0; mt < 6; mt++) {
                const float* Ab = As + (mt * 16) * 36;
                af[mt][0] = __float_as_uint(Ab[g * 36 + ko + t]);
                af[mt][1] = __float_as_uint(Ab[(g + 8) * 36 + ko + t]);
                af[mt][2] = __float_as_uint(Ab[g * 36 + ko + t + 4]);
                af[mt][3] = __float_as_uint(Ab[(g + 8) * 36 + ko + t + 4]);
            }
            #pragma unroll
            for (int j = 0; j < 2; j++) {
                unsigned b0 =
                    __float_as_uint(Wc[(wid * 16 + 8 * j + g) * 36 + ko + t]);
                unsigned b1 = __float_as_uint(
                    Wc[(wid * 16 + 8 * j + g) * 36 + ko + t + 4]);
                #pragma unroll
                for (int mt = 0; mt < 6; mt++)
                    mma_tf32(acc[mt][j][0], acc[mt][j][1], acc[mt][j][2],
                             acc[mt][j][3], af[mt][0], af[mt][1], af[mt][2],
                             af[mt][3], b0, b1);
            }
        }
        // expand stage st+1 (pairs 2st, 2st+1) into the other A buffer
        if (st + 1 < 13 && tid < 192) {
            int e = tid >> 1, pp = tid & 1;
            int p = 2 * st + pp;
            float D = SD[p * 98 + e];
            float* fr = sm + (((st + 1) & 1) ? E2_A1 : E2_A0) + e * 36 + pp * 16;
            rbf_gen<16, true>(D, 1.0f, fr, E_SINV, E_D2, E_E2);
        }
    }
    __syncthreads();

    float* h = sm;  // 96*128 = 12288 floats, aliases dead buffers
    #pragma unroll
    for (int mt = 0; mt < 6; mt++)
        #pragma unroll
        for (int j = 0; j < 2; j++) {
            int col = wid * 16 + 8 * j + 2 * t;
            *(float2*)(h + (mt * 16 + g) * 128 + col) =
                make_float2(acc[mt][j][0], acc[mt][j][1]);
            *(float2*)(h + (mt * 16 + g + 8) * 128 + col) =
                make_float2(acc[mt][j][2], acc[mt][j][3]);
        }
    __syncthreads();

    ln_epilogue96(h, ge, be, out, OFF_E, bx, wid, lane);
}

// ---------------------------------------------------------------------------
// Kernel 4: E_s via tf32 mma, 2 residues/block (M=96). 40 stages of 32 feats.
// Distances recomputed in the expansion (no seed tables).
// smem floats: W0[4608] W1[4608] A0[3456] A1[3456] = 16128 (64512 B).
// ---------------------------------------------------------------------------
#define ES2_W0 0
#define ES2_W1 4608
#define ES2_A0 9216
#define ES2_A1 12672
#define ES2_TOT 16128

__global__ void __launch_bounds__(256, 2) es_kernel(
    const float* __restrict__ X, const float* __restrict__ amask,
    const float* __restrict__ gs, const float* __restrict__ bs,
    float* __restrict__ out) {
    extern __shared__ float sm[];
    __shared__ int jn[96];
    __shared__ float anch[30];

    int bx = blockIdx.x;
    int tid = threadIdx.x;
    int wid = tid >> 5, lane = tid & 31;
    int g = lane >> 2, t = lane & 3;

    stage_ws_async(g_wsr, SF, 0, sm + ES2_W0, tid);
    cp_commit();

    if (tid < 96) jn[tid] = g_eidx[96 * bx + tid];
    if (tid >= 128 && tid < 158) anch[tid - 128] = g_coords[30 * bx + tid - 128];
    __syncthreads();

    // expansion of one stage's A tile (96 edges x 4 cells x 8 bins)
    auto expand = [&](int stage, float* An) {
        for (int task = tid; task < 384; task += 256) {
            int e = task >> 2, c4 = task & 3;
            int cell = 4 * stage + c4;
            int a = cell >> 5, s = cell & 31;
            int r = (e >= 48);
            int j = jn[e];
            size_t bi = (size_t)j * 37 + 5 + s;
            float x0 = X[bi * 3 + 0], x1 = X[bi * 3 + 1], x2 = X[bi * 3 + 2];
            float m = amask[bi];
            const float* ap = anch + r * 15 + a * 3;
            float dx = ap[0] - x0, dy = ap[1] - x1, dz = ap[2] - x2;
            float D = sqrtf(dx * dx + dy * dy + dz * dz + 1e-6f);
            rbf_gen<8, true>(D, m, An + e * 36 + c4 * 8, S_SINV, S_D2, S_E2);
        }
    };

    expand(0, sm + ES2_A0);

    float acc[6][2][4];
    #pragma unroll
    for (int mt = 0; mt < 6; mt++)
        #pragma unroll
        for (int j = 0; j < 2; j++)
            #pragma unroll
            for (int q = 0; q < 4; q++) acc[mt][j][q] = 0.0f;

    for (int st = 0; st < 40; st++) {
        cp_wait0();
        __syncthreads();
        if (st + 1 < 40) {
            stage_ws_async(g_wsr, SF, st + 1,
                           sm + (((st + 1) & 1) ? ES2_W1 : ES2_W0), tid);
            cp_commit();
        }
        const float* Wc = sm + ((st & 1) ? ES2_W1 : ES2_W0);
        const float* As = sm + ((st & 1) ? ES2_A1 : ES2_A0);
        #pragma unroll
        for (int k8 = 0; k8 < 4; k8++) {
            int ko = k8 * 8;
            unsigned af[6][4];
            #pragma unroll
            for (int mt = 0; mt < 6; mt++) {
                const float* Ab = As + (mt * 16) * 36;
                af[mt][0] = __float_as_uint(Ab[g * 36 + ko + t]);
                af[mt][1] = __float_as_uint(Ab[(g + 8) * 36 + ko + t]);
                af[mt][2] = __float_as_uint(Ab[g * 36 + ko + t + 4]);
                af[mt][3] = __float_as_uint(Ab[(g + 8) * 36 + ko + t + 4]);
            }
            #pragma unroll
            for (int j = 0; j < 2; j++) {
                unsigned b0 =
                    __float_as_uint(Wc[(wid * 16 + 8 * j + g) * 36 + ko + t]);
                unsigned b1 = __float_as_uint(
                    Wc[(wid * 16 + 8 * j + g) * 36 + ko + t + 4]);
                #pragma unroll
                for (int mt = 0; mt < 6; mt++)
                    mma_tf32(acc[mt][j][0], acc[mt][j][1], acc[mt][j][2],
                             acc[mt][j][3], af[mt][0], af[mt][1], af[mt][2],
                             af[mt][3], b0, b1);
            }
        }
        if (st + 1 < 40)
            expand(st + 1, sm + (((st + 1) & 1) ? ES2_A1 : ES2_A0));
    }
    __syncthreads();

    float* h = sm;  // 12288 floats, aliases dead buffers
    #pragma unroll
    for (int mt = 0; mt < 6; mt++)
        #pragma unroll
        for (int j = 0; j < 2; j++) {
            int col = wid * 16 + 8 * j + 2 * t;
            *(float2*)(h + (mt * 16 + g) * 128 + col) =
                make_float2(acc[mt][j][0], acc[mt][j][1]);
            *(float2*)(h + (mt * 16 + g + 8) * 128 + col) =
                make_float2(acc[mt][j][2], acc[mt][j][3]);
        }
    __syncthreads();

    ln_epilogue96(h, gs, bs, out, OFF_ES, bx, wid, lane);
}

// ---------------------------------------------------------------------------
extern "C" void kernel_launch(void* const* d_in, const int* in_sizes, int n_in,
                              void* d_out, int out_size) {
    (void)in_sizes; (void)n_in; (void)out_size;
    const float* X     = (const float*)d_in[0];
    const float* mask  = (const float*)d_in[2];
    const float* amask = (const float*)d_in[3];
    const int*   ridx  = (const int*)d_in[4];
    const int*   clab  = (const int*)d_in[6];
    const float* Wpos  = (const float*)d_in[7];
    const float* bpos  = (const float*)d_in[8];
    const float* We    = (const float*)d_in[9];
    const float* ge    = (const float*)d_in[10];
    const float* be    = (const float*)d_in[11];
    const float* Ws    = (const float*)d_in[12];
    const float* gs    = (const float*)d_in[13];
    const float* bs    = (const float*)d_in[14];
    float* out = (float*)d_out;

    int e_smem  = E2_TOT * 4;    // 73920
    int es_smem = ES2_TOT * 4;   // 64512
    cudaFuncSetAttribute(e_kernel, cudaFuncAttributeMaxDynamicSharedMemorySize,
                         e_smem);
    cudaFuncSetAttribute(es_kernel, cudaFuncAttributeMaxDynamicSharedMemorySize,
                         es_smem);

    geom_kernel<<<(LRES + 255) / 256, 256>>>(X);
    wcvt_kernel<<<(128 * SF + 255) / 256, 256>>>(Ws, We);
    topk_kernel<<<LRES, 256>>>(X, mask, out);
    e_kernel<<<LRES / 2, 256, e_smem>>>(Wpos, bpos, ridx, clab, ge, be, out);
    es_kernel<<<LRES / 2, 256, es_smem>>>(X, amask, gs, bs, out);
}

// round 14
// speedup vs baseline: 1.0675x; 1.0675x over previous
#include <cuda_runtime.h>

#define LRES 1024
#define TOPK 48
#define EF   416
#define SF   1280

#define OFF_E       0ull
#define OFF_EIDX    6291456ull
#define OFF_ES      6340608ull
#define OFF_EIDXSUB 12632064ull

__device__ float g_coords[LRES * 15];
__device__ int   g_eidx[LRES * TOPK];
__device__ float g_dnb[LRES * TOPK];
__device__ float g_wsr[128 * SF];   // tf32-rounded W_s
__device__ float g_wer[128 * EF];   // tf32-rounded W_e

__device__ __forceinline__ unsigned long long u64min_(unsigned long long a,
                                                      unsigned long long b) {
    return a < b ? a : b;
}

__device__ __forceinline__ void cp_commit() {
    asm volatile("cp.async.commit_group;" ::: "memory");
}
__device__ __forceinline__ void cp_wait0() {
    asm volatile("cp.async.wait_group 0;" ::: "memory");
}

__device__ __forceinline__ unsigned cvt_tf32(float x) {
    unsigned u;
    asm("cvt.rna.tf32.f32 %0, %1;" : "=r"(u) : "f"(x));
    return u;
}
__device__ __forceinline__ float tf32f(float x) {
    return __uint_as_float(cvt_tf32(x));
}

__device__ __forceinline__ void mma_tf32(float& d0, float& d1, float& d2,
                                         float& d3, unsigned a0, unsigned a1,
                                         unsigned a2, unsigned a3, unsigned b0,
                                         unsigned b1) {
    asm volatile(
        "mma.sync.aligned.m16n8k8.row.col.f32.tf32.tf32.f32 "
        "{%0,%1,%2,%3}, {%4,%5,%6,%7}, {%8,%9}, {%0,%1,%2,%3};"
        : "+f"(d0), "+f"(d1), "+f"(d2), "+f"(d3)
        : "r"(a0), "r"(a1), "r"(a2), "r"(a3), "r"(b0), "r"(b1));
}

// Chained RBF; ROUND -> store tf32-rounded values.
template <int NB, bool ROUND>
__device__ __forceinline__ void rbf_gen(float D, float m, float* __restrict__ fr,
                                        float SINV, float D2, float E2c) {
    float s = (D - 2.0f) * SINV;
    float v = __expf(-D2 * s * s);
    float g = __expf(D2 * (2.0f * s - 1.0f));
    float vals[NB];
    vals[0] = v;
    #pragma unroll
    for (int r = 1; r < NB; r++) { v *= g; g *= E2c; vals[r] = v; }
    if (vals[0] < 1e-30f) {
        float sN = s - (float)(NB - 1);
        float v1 = __expf(-D2 * sN * sN);
        float g1 = __expf(-D2 * (2.0f * sN + 1.0f));
        vals[NB - 1] = fmaxf(vals[NB - 1], v1);
        #pragma unroll
        for (int r = NB - 2; r >= 0; r--) {
            v1 *= g1; g1 *= E2c;
            vals[r] = fmaxf(vals[r], v1);
        }
    }
    #pragma unroll
    for (int r = 0; r < NB; r++)
        fr[r] = ROUND ? tf32f(m * vals[r]) : m * vals[r];
}

#define E_SINV 0.75f
#define E_D2   1.13777778f
#define E_E2   0.10273980f
#define S_SINV 0.35f
#define S_D2   1.30612245f
#define S_E2   0.07336966f

// stage 128ch x 32feat fp32 tile -> Wsm[ch*36 + f], 16B cp.async
__device__ __forceinline__ void stage_ws_async(const float* __restrict__ Wsrc,
                                               int stride, int st,
                                               float* __restrict__ Wsm,
                                               int tid) {
    #pragma unroll
    for (int p = tid; p < 1024; p += 256) {
        int ch = p >> 3, fc = p & 7;
        const float* src = Wsrc + ch * stride + st * 32 + fc * 4;
        unsigned int dst =
            (unsigned int)__cvta_generic_to_shared(Wsm + ch * 36 + fc * 4);
        asm volatile("cp.async.ca.shared.global [%0], [%1], 16;"
                     :: "r"(dst), "l"(src) : "memory");
    }
}

// ---------------------------------------------------------------------------
__global__ void wcvt_kernel(const float* __restrict__ Ws,
                            const float* __restrict__ We) {
    int i = blockIdx.x * 256 + threadIdx.x;
    if (i < 128 * SF) g_wsr[i] = tf32f(Ws[i]);
    if (i < 128 * EF) g_wer[i] = tf32f(We[i]);
}

// ---------------------------------------------------------------------------
__global__ void geom_kernel(const float* __restrict__ X) {
    int i = blockIdx.x * blockDim.x + threadIdx.x;
    if (i >= LRES) return;
    const float* xi = X + (size_t)i * 37 * 3;
    float n0 = xi[0],  n1 = xi[1],  n2 = xi[2];
    float a0 = xi[3],  a1 = xi[4],  a2 = xi[5];
    float c0 = xi[6],  c1 = xi[7],  c2 = xi[8];
    float o0 = xi[12], o1 = xi[13], o2 = xi[14];
    float b0 = a0 - n0, b1 = a1 - n1, b2 = a2 - n2;
    float d0 = c0 - a0, d1 = c1 - a1, d2 = c2 - a2;
    float x0 = b1 * d2 - b2 * d1;
    float x1 = b2 * d0 - b0 * d2;
    float x2 = b0 * d1 - b1 * d0;
    float cb0 = -0.58273431f * x0 + 0.56802827f * b0 - 0.54067466f * d0 + a0;
    float cb1 = -0.58273431f * x1 + 0.56802827f * b1 - 0.54067466f * d1 + a1;
    float cb2 = -0.58273431f * x2 + 0.56802827f * b2 - 0.54067466f * d2 + a2;
    float* dst = g_coords + i * 15;
    dst[0] = n0;  dst[1] = n1;  dst[2] = n2;
    dst[3] = a0;  dst[4] = a1;  dst[5] = a2;
    dst[6] = c0;  dst[7] = c1;  dst[8] = c2;
    dst[9] = o0;  dst[10] = o1; dst[11] = o2;
    dst[12] = cb0; dst[13] = cb1; dst[14] = cb2;
}

// ---------------------------------------------------------------------------
__global__ void topk_kernel(const float* __restrict__ X,
                            const float* __restrict__ mask,
                            float* __restrict__ out) {
    __shared__ float dsh[LRES];
    __shared__ unsigned long long keys[LRES];
    __shared__ float wmaxs[8];
    __shared__ unsigned long long wmins[8];
    __shared__ float smDmax;

    int i = blockIdx.x;
    int tid = threadIdx.x;
    float cax = X[((size_t)i * 37 + 1) * 3 + 0];
    float cay = X[((size_t)i * 37 + 1) * 3 + 1];
    float caz = X[((size_t)i * 37 + 1) * 3 + 2];
    float mi = mask[i];

    float lmax = 0.0f;
    for (int j = tid; j < LRES; j += 256) {
        float dx = cax - X[((size_t)j * 37 + 1) * 3 + 0];
        float dy = cay - X[((size_t)j * 37 + 1) * 3 + 1];
        float dz = caz - X[((size_t)j * 37 + 1) * 3 + 2];
        float s = dx * dx + dy * dy + dz * dz;
        float m2 = mi * mask[j];
        float Dv = m2 * sqrtf(s + 1e-6f);
        dsh[j] = Dv;
        lmax = fmaxf(lmax, Dv);
    }
    for (int off = 16; off; off >>= 1)
        lmax = fmaxf(lmax, __shfl_xor_sync(0xffffffffu, lmax, off));
    if ((tid & 31) == 0) wmaxs[tid >> 5] = lmax;
    __syncthreads();
    if (tid == 0) {
        float m = wmaxs[0];
        #pragma unroll
        for (int w = 1; w < 8; w++) m = fmaxf(m, wmaxs[w]);
        smDmax = m;
    }
    __syncthreads();
    float Dmax = smDmax;

    for (int j = tid; j < LRES; j += 256) {
        float m2 = mi * mask[j];
        float Dadj = dsh[j] + (1.0f - m2) * Dmax;
        keys[j] = (((unsigned long long)__float_as_uint(Dadj)) << 32) |
                  (unsigned int)j;
    }
    __syncthreads();

    for (int sel = 0; sel < TOPK; sel++) {
        unsigned long long lmin = 0xffffffffffffffffull;
        #pragma unroll
        for (int c = 0; c < 4; c++) lmin = u64min_(lmin, keys[tid + 256 * c]);
        for (int off = 16; off; off >>= 1) {
            unsigned long long o2 = __shfl_xor_sync(0xffffffffu, lmin, off);
            lmin = u64min_(lmin, o2);
        }
        if ((tid & 31) == 0) wmins[tid >> 5] = lmin;
        __syncthreads();
        if (tid == 0) {
            unsigned long long m = wmins[0];
            #pragma unroll
            for (int w = 1; w < 8; w++) m = u64min_(m, wmins[w]);
            int j = (int)(m & 0xffffffffull);
            float dv = __uint_as_float((unsigned int)(m >> 32));
            g_eidx[i * TOPK + sel] = j;
            g_dnb[i * TOPK + sel] = dv;
            out[OFF_EIDX + (size_t)i * TOPK + sel] = (float)j;
            out[OFF_EIDXSUB + (size_t)i * TOPK + sel] = (float)j;
            keys[j] = 0xffffffffffffffffull;
        }
        __syncthreads();
    }
}

// ---------------------------------------------------------------------------
// LN epilogue over NROW rows starting at global row row0.
template <int NROW>
__device__ __forceinline__ void ln_epilogue(const float* __restrict__ h,
                                            const float* __restrict__ gg,
                                            const float* __restrict__ bb,
                                            float* __restrict__ out,
                                            size_t off, int row0, int wid,
                                            int lane) {
    for (int k = wid; k < NROW; k += 8) {
        float v0 = h[k * 128 + lane];
        float v1 = h[k * 128 + lane + 32];
        float v2 = h[k * 128 + lane + 64];
        float v3 = h[k * 128 + lane + 96];
        float s = v0 + v1 + v2 + v3;
        for (int o = 16; o; o >>= 1) s += __shfl_xor_sync(0xffffffffu, s, o);
        float mu = s * (1.0f / 128.0f);
        float d0 = v0 - mu, d1 = v1 - mu, d2 = v2 - mu, d3 = v3 - mu;
        float s2 = d0 * d0 + d1 * d1 + d2 * d2 + d3 * d3;
        for (int o = 16; o; o >>= 1) s2 += __shfl_xor_sync(0xffffffffu, s2, o);
        float inv = rsqrtf(s2 * (1.0f / 128.0f) + 1e-5f);
        size_t base = off + ((size_t)(row0 + k)) * 128;
        out[base + lane]      = gg[lane]      * d0 * inv + bb[lane];
        out[base + lane + 32] = gg[lane + 32] * d1 * inv + bb[lane + 32];
        out[base + lane + 64] = gg[lane + 64] * d2 * inv + bb[lane + 64];
        out[base + lane + 96] = gg[lane + 96] * d3 * inv + bb[lane + 96];
    }
}

// ---------------------------------------------------------------------------
// Fused feature kernel. Blocks [0,512): E role (2 residues, M=96).
// Blocks [512,1536): E_s role (1 residue, M=48, seed tables).
// Unified dynamic smem = 28352 floats (113408 B).
//
// E layout  (floats): W0[4608] W1[4608] A0[3456] A1[3456] SD[2352] = 18480
// Es layout (floats): W0[4608] W1[4608] A0[1728] A1[1728] SDv[7840] SDg[7840]
#define U_TOT 28352
#define E2_W0 0
#define E2_W1 4608
#define E2_A0 9216
#define E2_A1 12672
#define E2_SD 16128
#define ES_W0 0
#define ES_W1 4608
#define ES_A0 9216
#define ES_A1 10944
#define ES_SDV 12672
#define ES_SDG 20512

__global__ void __launch_bounds__(256, 2) feat_kernel(
    const float* __restrict__ X, const float* __restrict__ amask,
    const int* __restrict__ ridx, const int* __restrict__ clab,
    const float* __restrict__ Wpos, const float* __restrict__ bpos,
    const float* __restrict__ ge, const float* __restrict__ be,
    const float* __restrict__ gs, const float* __restrict__ bs,
    float* __restrict__ out) {
    extern __shared__ float sm[];
    __shared__ int jn[96];
    __shared__ float anch[30];

    int tid = threadIdx.x;
    int wid = tid >> 5, lane = tid & 31;
    int g = lane >> 2, t = lane & 3;

    if (blockIdx.x < 512) {
        // ------------------------- E role (M=96) --------------------------
        int bx = blockIdx.x;
        float* SD = sm + E2_SD;

        stage_ws_async(g_wer, EF, 0, sm + E2_W0, tid);
        cp_commit();

        if (tid < 96) {
            int e = tid;
            int r = (e >= 48);
            int ires = 2 * bx + r;
            int j = g_eidx[96 * bx + e];
            int offr = ridx[ires] - ridx[j];
            int ec = (clab[ires] == clab[j]) ? 1 : 0;
            int d = min(max(offr + 32, 0), 64) * ec + (1 - ec) * 65;
            float* fr = sm + E2_A0 + e * 36;
            #pragma unroll
            for (int f = 0; f < 16; f++)
                fr[f] = tf32f(Wpos[f * 66 + d] + bpos[f]);
            rbf_gen<16, true>(g_dnb[96 * bx + e], 1.0f, fr + 16, E_SINV, E_D2,
                              E_E2);
        }

        const signed char pa[24] =
            {0,2,3,4,1,1,1,1,0,0,0,4,4,3,0,2,3,4,2,3,4,2,3,2};
        const signed char pb[24] =
            {0,2,3,4,0,2,3,4,2,3,4,2,3,2,1,1,1,1,0,0,0,4,4,3};
        for (int tt = tid; tt < 96 * 24; tt += 256) {
            int k = tt / 24, p = tt - k * 24;
            int r = (k >= 48);
            int ires = 2 * bx + r;
            int j = g_eidx[96 * bx + k];
            const float* A = g_coords + ires * 15 + (int)pa[p] * 3;
            const float* B = g_coords + j * 15 + (int)pb[p] * 3;
            float dx = A[0] - B[0], dy = A[1] - B[1], dz = A[2] - B[2];
            SD[p * 98 + k] = sqrtf(dx * dx + dy * dy + dz * dz + 1e-6f);
        }

        float acc[6][2][4];
        #pragma unroll
        for (int mt = 0; mt < 6; mt++)
            #pragma unroll
            for (int j = 0; j < 2; j++)
                #pragma unroll
                for (int q = 0; q < 4; q++) acc[mt][j][q] = 0.0f;

        for (int st = 0; st < 13; st++) {
            cp_wait0();
            __syncthreads();
            if (st + 1 < 13) {
                stage_ws_async(g_wer, EF, st + 1,
                               sm + (((st + 1) & 1) ? E2_W1 : E2_W0), tid);
                cp_commit();
            }
            const float* Wc = sm + ((st & 1) ? E2_W1 : E2_W0);
            const float* As = sm + ((st & 1) ? E2_A1 : E2_A0);
            #pragma unroll
            for (int k8 = 0; k8 < 4; k8++) {
                int ko = k8 * 8;
                unsigned af[6][4];
                #pragma unroll
                for (int mt = 0; mt < 6; mt++) {
                    const float* Ab = As + (mt * 16) * 36;
                    af[mt][0] = __float_as_uint(Ab[g * 36 + ko + t]);
                    af[mt][1] = __float_as_uint(Ab[(g + 8) * 36 + ko + t]);
                    af[mt][2] = __float_as_uint(Ab[g * 36 + ko + t + 4]);
                    af[mt][3] = __float_as_uint(Ab[(g + 8) * 36 + ko + t + 4]);
                }
                #pragma unroll
                for (int j = 0; j < 2; j++) {
                    unsigned b0 = __float_as_uint(
                        Wc[(wid * 16 + 8 * j + g) * 36 + ko + t]);
                    unsigned b1 = __float_as_uint(
                        Wc[(wid * 16 + 8 * j + g) * 36 + ko + t + 4]);
                    #pragma unroll
                    for (int mt = 0; mt < 6; mt++)
                        mma_tf32(acc[mt][j][0], acc[mt][j][1], acc[mt][j][2],
                                 acc[mt][j][3], af[mt][0], af[mt][1],
                                 af[mt][2], af[mt][3], b0, b1);
                }
            }
            if (st + 1 < 13 && tid < 192) {
                int e = tid >> 1, pp = tid & 1;
                int p = 2 * st + pp;
                float D = SD[p * 98 + e];
                float* fr =
                    sm + (((st + 1) & 1) ? E2_A1 : E2_A0) + e * 36 + pp * 16;
                rbf_gen<16, true>(D, 1.0f, fr, E_SINV, E_D2, E_E2);
            }
        }
        __syncthreads();

        float* h = sm;
        #pragma unroll
        for (int mt = 0; mt < 6; mt++)
            #pragma unroll
            for (int j = 0; j < 2; j++) {
                int col = wid * 16 + 8 * j + 2 * t;
                *(float2*)(h + (mt * 16 + g) * 128 + col) =
                    make_float2(acc[mt][j][0], acc[mt][j][1]);
                *(float2*)(h + (mt * 16 + g + 8) * 128 + col) =
                    make_float2(acc[mt][j][2], acc[mt][j][3]);
            }
        __syncthreads();

        ln_epilogue<96>(h, ge, be, out, OFF_E, 96 * bx, wid, lane);
    } else {
        // ------------------------ E_s role (M=48) -------------------------
        int i = blockIdx.x - 512;
        float* SDv = sm + ES_SDV;
        float* SDg = sm + ES_SDG;

        stage_ws_async(g_wsr, SF, 0, sm + ES_W0, tid);
        cp_commit();

        if (tid < TOPK) jn[tid] = g_eidx[i * TOPK + tid];
        if (tid >= 64 && tid < 79)
            anch[tid - 64] = g_coords[i * 15 + (tid - 64)];
        __syncthreads();

        #pragma unroll
        for (int it = 0; it < 6; it++) {
            int task = tid + 256 * it;
            int e = task >> 5, s = task & 31;
            int j = jn[e];
            size_t bi = (size_t)j * 37 + 5 + s;
            float x0 = X[bi * 3 + 0], x1 = X[bi * 3 + 1], x2 = X[bi * 3 + 2];
            float m = amask[bi];
            #pragma unroll
            for (int a = 0; a < 5; a++) {
                float dx = anch[a * 3 + 0] - x0;
                float dy = anch[a * 3 + 1] - x1;
                float dz = anch[a * 3 + 2] - x2;
                float D = sqrtf(dx * dx + dy * dy + dz * dz + 1e-6f);
                float sc = (D - 2.0f) * S_SINV;
                float v = m * __expf(-S_D2 * sc * sc);
                float gg = __expf(S_D2 * (2.0f * sc - 1.0f));
                int cell = a * 32 + s;
                SDv[cell * 49 + e] = v;
                SDg[cell * 49 + e] = gg;
            }
        }
        __syncthreads();

        if (tid < 192) {
            int e = tid >> 2, c4 = tid & 3;
            float v = SDv[c4 * 49 + e];
            float gg = SDg[c4 * 49 + e];
            float vals[8];
            vals[0] = v;
            #pragma unroll
            for (int r = 1; r < 8; r++) { v *= gg; gg *= S_E2; vals[r] = v; }
            float4 f0, f1;
            f0.x = tf32f(vals[0]); f0.y = tf32f(vals[1]);
            f0.z = tf32f(vals[2]); f0.w = tf32f(vals[3]);
            f1.x = tf32f(vals[4]); f1.y = tf32f(vals[5]);
            f1.z = tf32f(vals[6]); f1.w = tf32f(vals[7]);
            *(float4*)(sm + ES_A0 + e * 36 + c4 * 8) = f0;
            *(float4*)(sm + ES_A0 + e * 36 + c4 * 8 + 4) = f1;
        }

        int n0 = wid * 16;
        float acc[3][2][4];
        #pragma unroll
        for (int mt = 0; mt < 3; mt++)
            #pragma unroll
            for (int j = 0; j < 2; j++)
                #pragma unroll
                for (int q = 0; q < 4; q++) acc[mt][j][q] = 0.0f;

        for (int st = 0; st < 40; st++) {
            cp_wait0();
            __syncthreads();
            if (st + 1 < 40) {
                stage_ws_async(g_wsr, SF, st + 1,
                               sm + (((st + 1) & 1) ? ES_W1 : ES_W0), tid);
                cp_commit();
            }
            const float* Wc = sm + ((st & 1) ? ES_W1 : ES_W0);
            const float* As = sm + ((st & 1) ? ES_A1 : ES_A0);
            #pragma unroll
            for (int k8 = 0; k8 < 4; k8++) {
                int ko = k8 * 8;
                unsigned af[3][4];
                #pragma unroll
                for (int mt = 0; mt < 3; mt++) {
                    const float* Ab = As + (mt * 16) * 36;
                    af[mt][0] = __float_as_uint(Ab[g * 36 + ko + t]);
                    af[mt][1] = __float_as_uint(Ab[(g + 8) * 36 + ko + t]);
                    af[mt][2] = __float_as_uint(Ab[g * 36 + ko + t + 4]);
                    af[mt][3] = __float_as_uint(Ab[(g + 8) * 36 + ko + t + 4]);
                }
                #pragma unroll
                for (int j = 0; j < 2; j++) {
                    unsigned b0 =
                        __float_as_uint(Wc[(n0 + 8 * j + g) * 36 + ko + t]);
                    unsigned b1 =
                        __float_as_uint(Wc[(n0 + 8 * j + g) * 36 + ko + t + 4]);
                    #pragma unroll
                    for (int mt = 0; mt < 3; mt++)
                        mma_tf32(acc[mt][j][0], acc[mt][j][1], acc[mt][j][2],
                                 acc[mt][j][3], af[mt][0], af[mt][1],
                                 af[mt][2], af[mt][3], b0, b1);
                }
            }
            if (st + 1 < 40 && tid < 192) {
                int e = tid >> 2, c4 = tid & 3;
                int cell = 4 * (st + 1) + c4;
                float v = SDv[cell * 49 + e];
                float gg = SDg[cell * 49 + e];
                float vals[8];
                vals[0] = v;
                #pragma unroll
                for (int r = 1; r < 8; r++) { v *= gg; gg *= S_E2; vals[r] = v; }
                float4 f0, f1;
                f0.x = tf32f(vals[0]); f0.y = tf32f(vals[1]);
                f0.z = tf32f(vals[2]); f0.w = tf32f(vals[3]);
                f1.x = tf32f(vals[4]); f1.y = tf32f(vals[5]);
                f1.z = tf32f(vals[6]); f1.w = tf32f(vals[7]);
                float* An = sm + (((st + 1) & 1) ? ES_A1 : ES_A0);
                *(float4*)(An + e * 36 + c4 * 8) = f0;
                *(float4*)(An + e * 36 + c4 * 8 + 4) = f1;
            }
        }
        __syncthreads();

        float* h = SDv;
        #pragma unroll
        for (int mt = 0; mt < 3; mt++)
            #pragma unroll
            for (int j = 0; j < 2; j++) {
                int col = n0 + 8 * j + 2 * t;
                *(float2*)(h + (mt * 16 + g) * 128 + col) =
                    make_float2(acc[mt][j][0], acc[mt][j][1]);
                *(float2*)(h + (mt * 16 + g + 8) * 128 + col) =
                    make_float2(acc[mt][j][2], acc[mt][j][3]);
            }
        __syncthreads();

        ln_epilogue<48>(h, gs, bs, out, OFF_ES, i * TOPK, wid, lane);
    }
}

// ---------------------------------------------------------------------------
extern "C" void kernel_launch(void* const* d_in, const int* in_sizes, int n_in,
                              void* d_out, int out_size) {
    (void)in_sizes; (void)n_in; (void)out_size;
    const float* X     = (const float*)d_in[0];
    const float* mask  = (const float*)d_in[2];
    const float* amask = (const float*)d_in[3];
    const int*   ridx  = (const int*)d_in[4];
    const int*   clab  = (const int*)d_in[6];
    const float* Wpos  = (const float*)d_in[7];
    const float* bpos  = (const float*)d_in[8];
    const float* We    = (const float*)d_in[9];
    const float* ge    = (const float*)d_in[10];
    const float* be    = (const float*)d_in[11];
    const float* Ws    = (const float*)d_in[12];
    const float* gs    = (const float*)d_in[13];
    const float* bs    = (const float*)d_in[14];
    float* out = (float*)d_out;

    int u_smem = U_TOT * 4;   // 113408
    cudaFuncSetAttribute(feat_kernel,
                         cudaFuncAttributeMaxDynamicSharedMemorySize, u_smem);

    geom_kernel<<<(LRES + 255) / 256, 256>>>(X);
    wcvt_kernel<<<(128 * SF + 255) / 256, 256>>>(Ws, We);
    topk_kernel<<<LRES, 256>>>(X, mask, out);
    feat_kernel<<<512 + LRES, 256, u_smem>>>(X, amask, ridx, clab, Wpos, bpos,
                                             ge, be, gs, bs, out);
}

// round 15
// speedup vs baseline: 1.2160x; 1.1390x over previous
#include <cuda_runtime.h>

#define LRES 1024
#define TOPK 48
#define EF   416
#define SF   1280

#define OFF_E       0ull
#define OFF_EIDX    6291456ull
#define OFF_ES      6340608ull
#define OFF_EIDXSUB 12632064ull

__device__ float g_coords[LRES * 15];
__device__ int   g_eidx[LRES * TOPK];
__device__ float g_dnb[LRES * TOPK];
__device__ float g_wsr[128 * SF];   // tf32-rounded W_s
__device__ float g_wer[128 * EF];   // tf32-rounded W_e

__device__ __forceinline__ unsigned long long u64min_(unsigned long long a,
                                                      unsigned long long b) {
    return a < b ? a : b;
}

__device__ __forceinline__ unsigned long long warpmin_u64(unsigned long long v) {
    #pragma unroll
    for (int o = 16; o; o >>= 1) {
        unsigned long long w = __shfl_xor_sync(0xffffffffu, v, o);
        v = u64min_(v, w);
    }
    return v;
}

__device__ __forceinline__ void cp_commit() {
    asm volatile("cp.async.commit_group;" ::: "memory");
}
__device__ __forceinline__ void cp_wait0() {
    asm volatile("cp.async.wait_group 0;" ::: "memory");
}

__device__ __forceinline__ unsigned cvt_tf32(float x) {
    unsigned u;
    asm("cvt.rna.tf32.f32 %0, %1;" : "=r"(u) : "f"(x));
    return u;
}
__device__ __forceinline__ float tf32f(float x) {
    return __uint_as_float(cvt_tf32(x));
}

__device__ __forceinline__ void mma_tf32(float& d0, float& d1, float& d2,
                                         float& d3, unsigned a0, unsigned a1,
                                         unsigned a2, unsigned a3, unsigned b0,
                                         unsigned b1) {
    asm volatile(
        "mma.sync.aligned.m16n8k8.row.col.f32.tf32.tf32.f32 "
        "{%0,%1,%2,%3}, {%4,%5,%6,%7}, {%8,%9}, {%0,%1,%2,%3};"
        : "+f"(d0), "+f"(d1), "+f"(d2), "+f"(d3)
        : "r"(a0), "r"(a1), "r"(a2), "r"(a3), "r"(b0), "r"(b1));
}

// Chained RBF; ROUND -> store tf32-rounded values.
template <int NB, bool ROUND>
__device__ __forceinline__ void rbf_gen(float D, float m, float* __restrict__ fr,
                                        float SINV, float D2, float E2c) {
    float s = (D - 2.0f) * SINV;
    float v = __expf(-D2 * s * s);
    float g = __expf(D2 * (2.0f * s - 1.0f));
    float vals[NB];
    vals[0] = v;
    #pragma unroll
    for (int r = 1; r < NB; r++) { v *= g; g *= E2c; vals[r] = v; }
    if (vals[0] < 1e-30f) {
        float sN = s - (float)(NB - 1);
        float v1 = __expf(-D2 * sN * sN);
        float g1 = __expf(-D2 * (2.0f * sN + 1.0f));
        vals[NB - 1] = fmaxf(vals[NB - 1], v1);
        #pragma unroll
        for (int r = NB - 2; r >= 0; r--) {
            v1 *= g1; g1 *= E2c;
            vals[r] = fmaxf(vals[r], v1);
        }
    }
    #pragma unroll
    for (int r = 0; r < NB; r++)
        fr[r] = ROUND ? tf32f(m * vals[r]) : m * vals[r];
}

#define E_SINV 0.75f
#define E_D2   1.13777778f
#define E_E2   0.10273980f
#define S_SINV 0.35f
#define S_D2   1.30612245f
#define S_E2   0.07336966f

// stage 128ch x 32feat fp32 tile -> Wsm[ch*36 + f], 16B cp.async
__device__ __forceinline__ void stage_ws_async(const float* __restrict__ Wsrc,
                                               int stride, int st,
                                               float* __restrict__ Wsm,
                                               int tid) {
    #pragma unroll
    for (int p = tid; p < 1024; p += 256) {
        int ch = p >> 3, fc = p & 7;
        const float* src = Wsrc + ch * stride + st * 32 + fc * 4;
        unsigned int dst =
            (unsigned int)__cvta_generic_to_shared(Wsm + ch * 36 + fc * 4);
        asm volatile("cp.async.ca.shared.global [%0], [%1], 16;"
                     :: "r"(dst), "l"(src) : "memory");
    }
}

// ---------------------------------------------------------------------------
__global__ void wcvt_kernel(const float* __restrict__ Ws,
                            const float* __restrict__ We) {
    int i = blockIdx.x * 256 + threadIdx.x;
    if (i < 128 * SF) g_wsr[i] = tf32f(Ws[i]);
    if (i < 128 * EF) g_wer[i] = tf32f(We[i]);
}

// ---------------------------------------------------------------------------
__global__ void geom_kernel(const float* __restrict__ X) {
    int i = blockIdx.x * blockDim.x + threadIdx.x;
    if (i >= LRES) return;
    const float* xi = X + (size_t)i * 37 * 3;
    float n0 = xi[0],  n1 = xi[1],  n2 = xi[2];
    float a0 = xi[3],  a1 = xi[4],  a2 = xi[5];
    float c0 = xi[6],  c1 = xi[7],  c2 = xi[8];
    float o0 = xi[12], o1 = xi[13], o2 = xi[14];
    float b0 = a0 - n0, b1 = a1 - n1, b2 = a2 - n2;
    float d0 = c0 - a0, d1 = c1 - a1, d2 = c2 - a2;
    float x0 = b1 * d2 - b2 * d1;
    float x1 = b2 * d0 - b0 * d2;
    float x2 = b0 * d1 - b1 * d0;
    float cb0 = -0.58273431f * x0 + 0.56802827f * b0 - 0.54067466f * d0 + a0;
    float cb1 = -0.58273431f * x1 + 0.56802827f * b1 - 0.54067466f * d1 + a1;
    float cb2 = -0.58273431f * x2 + 0.56802827f * b2 - 0.54067466f * d2 + a2;
    float* dst = g_coords + i * 15;
    dst[0] = n0;  dst[1] = n1;  dst[2] = n2;
    dst[3] = a0;  dst[4] = a1;  dst[5] = a2;
    dst[6] = c0;  dst[7] = c1;  dst[8] = c2;
    dst[9] = o0;  dst[10] = o1; dst[11] = o2;
    dst[12] = cb0; dst[13] = cb1; dst[14] = cb2;
}

// ---------------------------------------------------------------------------
// topk with chunk-minima cache: distance phase parallel, selection 1 warp.
__global__ void topk_kernel(const float* __restrict__ X,
                            const float* __restrict__ mask,
                            float* __restrict__ out) {
    __shared__ float dsh[LRES];
    __shared__ unsigned long long keys[LRES];
    __shared__ unsigned long long cmin[32];
    __shared__ float wmaxs[8];
    __shared__ float smDmax;

    int i = blockIdx.x;
    int tid = threadIdx.x;
    int wid = tid >> 5, lane = tid & 31;
    float cax = X[((size_t)i * 37 + 1) * 3 + 0];
    float cay = X[((size_t)i * 37 + 1) * 3 + 1];
    float caz = X[((size_t)i * 37 + 1) * 3 + 2];
    float mi = mask[i];

    float lmax = 0.0f;
    for (int j = tid; j < LRES; j += 256) {
        float dx = cax - X[((size_t)j * 37 + 1) * 3 + 0];
        float dy = cay - X[((size_t)j * 37 + 1) * 3 + 1];
        float dz = caz - X[((size_t)j * 37 + 1) * 3 + 2];
        float s = dx * dx + dy * dy + dz * dz;
        float m2 = mi * mask[j];
        float Dv = m2 * sqrtf(s + 1e-6f);
        dsh[j] = Dv;
        lmax = fmaxf(lmax, Dv);
    }
    for (int off = 16; off; off >>= 1)
        lmax = fmaxf(lmax, __shfl_xor_sync(0xffffffffu, lmax, off));
    if (lane == 0) wmaxs[wid] = lmax;
    __syncthreads();
    if (tid == 0) {
        float m = wmaxs[0];
        #pragma unroll
        for (int w = 1; w < 8; w++) m = fmaxf(m, wmaxs[w]);
        smDmax = m;
    }
    __syncthreads();
    float Dmax = smDmax;

    for (int j = tid; j < LRES; j += 256) {
        float m2 = mi * mask[j];
        float Dadj = dsh[j] + (1.0f - m2) * Dmax;
        keys[j] = (((unsigned long long)__float_as_uint(Dadj)) << 32) |
                  (unsigned int)j;
    }
    __syncthreads();

    // chunk minima: chunk c = keys[32c..32c+31]; warp w builds chunks 4w..4w+3
    #pragma unroll
    for (int q = 0; q < 4; q++) {
        int c = wid * 4 + q;
        unsigned long long v = keys[c * 32 + lane];
        v = warpmin_u64(v);
        if (lane == 0) cmin[c] = v;
    }
    __syncthreads();

    if (wid == 0) {
        for (int sel = 0; sel < TOPK; sel++) {
            unsigned long long v = cmin[lane];
            unsigned long long m = warpmin_u64(v);
            int j = (int)(m & 0xffffffffull);
            if (lane == 0) {
                float dv = __uint_as_float((unsigned int)(m >> 32));
                g_eidx[i * TOPK + sel] = j;
                g_dnb[i * TOPK + sel] = dv;
                out[OFF_EIDX + (size_t)i * TOPK + sel] = (float)j;
                out[OFF_EIDXSUB + (size_t)i * TOPK + sel] = (float)j;
                keys[j] = 0xffffffffffffffffull;
            }
            __syncwarp();
            int c = j >> 5;
            unsigned long long kv = keys[c * 32 + lane];
            kv = warpmin_u64(kv);
            if (lane == 0) cmin[c] = kv;
            __syncwarp();
        }
    }
}

// ---------------------------------------------------------------------------
// LN epilogue over NROW rows starting at global row row0.
template <int NROW>
__device__ __forceinline__ void ln_epilogue(const float* __restrict__ h,
                                            const float* __restrict__ gg,
                                            const float* __restrict__ bb,
                                            float* __restrict__ out,
                                            size_t off, int row0, int wid,
                                            int lane) {
    for (int k = wid; k < NROW; k += 8) {
        float v0 = h[k * 128 + lane];
        float v1 = h[k * 128 + lane + 32];
        float v2 = h[k * 128 + lane + 64];
        float v3 = h[k * 128 + lane + 96];
        float s = v0 + v1 + v2 + v3;
        for (int o = 16; o; o >>= 1) s += __shfl_xor_sync(0xffffffffu, s, o);
        float mu = s * (1.0f / 128.0f);
        float d0 = v0 - mu, d1 = v1 - mu, d2 = v2 - mu, d3 = v3 - mu;
        float s2 = d0 * d0 + d1 * d1 + d2 * d2 + d3 * d3;
        for (int o = 16; o; o >>= 1) s2 += __shfl_xor_sync(0xffffffffu, s2, o);
        float inv = rsqrtf(s2 * (1.0f / 128.0f) + 1e-5f);
        size_t base = off + ((size_t)(row0 + k)) * 128;
        out[base + lane]      = gg[lane]      * d0 * inv + bb[lane];
        out[base + lane + 32] = gg[lane + 32] * d1 * inv + bb[lane + 32];
        out[base + lane + 64] = gg[lane + 64] * d2 * inv + bb[lane + 64];
        out[base + lane + 96] = gg[lane + 96] * d3 * inv + bb[lane + 96];
    }
}

// ---------------------------------------------------------------------------
// Fused feature kernel. Blocks [0,512): E role (2 residues, M=96).
// Blocks [512,1536): E_s role (1 residue, M=48, seed tables).
// Unified dynamic smem = 28352 floats (113408 B).
#define U_TOT 28352
#define E2_W0 0
#define E2_W1 4608
#define E2_A0 9216
#define E2_A1 12672
#define E2_SD 16128
#define ES_W0 0
#define ES_W1 4608
#define ES_A0 9216
#define ES_A1 10944
#define ES_SDV 12672
#define ES_SDG 20512

__global__ void __launch_bounds__(256, 2) feat_kernel(
    const float* __restrict__ X, const float* __restrict__ amask,
    const int* __restrict__ ridx, const int* __restrict__ clab,
    const float* __restrict__ Wpos, const float* __restrict__ bpos,
    const float* __restrict__ ge, const float* __restrict__ be,
    const float* __restrict__ gs, const float* __restrict__ bs,
    float* __restrict__ out) {
    extern __shared__ float sm[];
    __shared__ int jn[96];
    __shared__ float anch[30];

    int tid = threadIdx.x;
    int wid = tid >> 5, lane = tid & 31;
    int g = lane >> 2, t = lane & 3;

    if (blockIdx.x < 512) {
        // ---------------- E role (M=96): warp = (N32-group, M-half) --------
        int bx = blockIdx.x;
        float* SD = sm + E2_SD;
        int ng = wid & 3, mh = wid >> 2;

        stage_ws_async(g_wer, EF, 0, sm + E2_W0, tid);
        cp_commit();

        if (tid < 96) {
            int e = tid;
            int r = (e >= 48);
            int ires = 2 * bx + r;
            int j = g_eidx[96 * bx + e];
            int offr = ridx[ires] - ridx[j];
            int ec = (clab[ires] == clab[j]) ? 1 : 0;
            int d = min(max(offr + 32, 0), 64) * ec + (1 - ec) * 65;
            float* fr = sm + E2_A0 + e * 36;
            #pragma unroll
            for (int f = 0; f < 16; f++)
                fr[f] = tf32f(Wpos[f * 66 + d] + bpos[f]);
            rbf_gen<16, true>(g_dnb[96 * bx + e], 1.0f, fr + 16, E_SINV, E_D2,
                              E_E2);
        }

        const signed char pa[24] =
            {0,2,3,4,1,1,1,1,0,0,0,4,4,3,0,2,3,4,2,3,4,2,3,2};
        const signed char pb[24] =
            {0,2,3,4,0,2,3,4,2,3,4,2,3,2,1,1,1,1,0,0,0,4,4,3};
        for (int tt = tid; tt < 96 * 24; tt += 256) {
            int k = tt / 24, p = tt - k * 24;
            int r = (k >= 48);
            int ires = 2 * bx + r;
            int j = g_eidx[96 * bx + k];
            const float* A = g_coords + ires * 15 + (int)pa[p] * 3;
            const float* B = g_coords + j * 15 + (int)pb[p] * 3;
            float dx = A[0] - B[0], dy = A[1] - B[1], dz = A[2] - B[2];
            SD[p * 98 + k] = sqrtf(dx * dx + dy * dy + dz * dz + 1e-6f);
        }

        float acc[3][4][4];
        #pragma unroll
        for (int mt = 0; mt < 3; mt++)
            #pragma unroll
            for (int j = 0; j < 4; j++)
                #pragma unroll
                for (int q = 0; q < 4; q++) acc[mt][j][q] = 0.0f;

        for (int st = 0; st < 13; st++) {
            cp_wait0();
            __syncthreads();
            if (st + 1 < 13) {
                stage_ws_async(g_wer, EF, st + 1,
                               sm + (((st + 1) & 1) ? E2_W1 : E2_W0), tid);
                cp_commit();
            }
            const float* Wc = sm + ((st & 1) ? E2_W1 : E2_W0);
            const float* As = sm + ((st & 1) ? E2_A1 : E2_A0);
            #pragma unroll
            for (int k8 = 0; k8 < 4; k8++) {
                int ko = k8 * 8;
                unsigned af[3][4];
                #pragma unroll
                for (int mt = 0; mt < 3; mt++) {
                    const float* Ab = As + ((mh * 3 + mt) * 16) * 36;
                    af[mt][0] = __float_as_uint(Ab[g * 36 + ko + t]);
                    af[mt][1] = __float_as_uint(Ab[(g + 8) * 36 + ko + t]);
                    af[mt][2] = __float_as_uint(Ab[g * 36 + ko + t + 4]);
                    af[mt][3] = __float_as_uint(Ab[(g + 8) * 36 + ko + t + 4]);
                }
                #pragma unroll
                for (int j = 0; j < 4; j++) {
                    unsigned b0 = __float_as_uint(
                        Wc[(32 * ng + 8 * j + g) * 36 + ko + t]);
                    unsigned b1 = __float_as_uint(
                        Wc[(32 * ng + 8 * j + g) * 36 + ko + t + 4]);
                    #pragma unroll
                    for (int mt = 0; mt < 3; mt++)
                        mma_tf32(acc[mt][j][0], acc[mt][j][1], acc[mt][j][2],
                                 acc[mt][j][3], af[mt][0], af[mt][1],
                                 af[mt][2], af[mt][3], b0, b1);
                }
            }
            if (st + 1 < 13 && tid < 192) {
                int e = tid >> 1, pp = tid & 1;
                int p = 2 * st + pp;
                float D = SD[p * 98 + e];
                float* fr =
                    sm + (((st + 1) & 1) ? E2_A1 : E2_A0) + e * 36 + pp * 16;
                rbf_gen<16, true>(D, 1.0f, fr, E_SINV, E_D2, E_E2);
            }
        }
        __syncthreads();

        float* h = sm;
        #pragma unroll
        for (int mt = 0; mt < 3; mt++)
            #pragma unroll
            for (int j = 0; j < 4; j++) {
                int col = 32 * ng + 8 * j + 2 * t;
                int row = (mh * 3 + mt) * 16 + g;
                *(float2*)(h + row * 128 + col) =
                    make_float2(acc[mt][j][0], acc[mt][j][1]);
                *(float2*)(h + (row + 8) * 128 + col) =
                    make_float2(acc[mt][j][2], acc[mt][j][3]);
            }
        __syncthreads();

        ln_epilogue<96>(h, ge, be, out, OFF_E, 96 * bx, wid, lane);
    } else {
        // ---------------- E_s role (M=48): warp = (N32-group, k8-half) -----
        int i = blockIdx.x - 512;
        float* SDv = sm + ES_SDV;
        float* SDg = sm + ES_SDG;
        int ng = wid & 3, kh = wid >> 2;

        stage_ws_async(g_wsr, SF, 0, sm + ES_W0, tid);
        cp_commit();

        if (tid < TOPK) jn[tid] = g_eidx[i * TOPK + tid];
        if (tid >= 64 && tid < 79)
            anch[tid - 64] = g_coords[i * 15 + (tid - 64)];
        __syncthreads();

        #pragma unroll
        for (int it = 0; it < 6; it++) {
            int task = tid + 256 * it;
            int e = task >> 5, s = task & 31;
            int j = jn[e];
            size_t bi = (size_t)j * 37 + 5 + s;
            float x0 = X[bi * 3 + 0], x1 = X[bi * 3 + 1], x2 = X[bi * 3 + 2];
            float m = amask[bi];
            #pragma unroll
            for (int a = 0; a < 5; a++) {
                float dx = anch[a * 3 + 0] - x0;
                float dy = anch[a * 3 + 1] - x1;
                float dz = anch[a * 3 + 2] - x2;
                float D = sqrtf(dx * dx + dy * dy + dz * dz + 1e-6f);
                float sc = (D - 2.0f) * S_SINV;
                float v = m * __expf(-S_D2 * sc * sc);
                float gg = __expf(S_D2 * (2.0f * sc - 1.0f));
                int cell = a * 32 + s;
                SDv[cell * 49 + e] = v;
                SDg[cell * 49 + e] = gg;
            }
        }
        __syncthreads();

        if (tid < 192) {
            int e = tid >> 2, c4 = tid & 3;
            float v = SDv[c4 * 49 + e];
            float gg = SDg[c4 * 49 + e];
            float vals[8];
            vals[0] = v;
            #pragma unroll
            for (int r = 1; r < 8; r++) { v *= gg; gg *= S_E2; vals[r] = v; }
            float4 f0, f1;
            f0.x = tf32f(vals[0]); f0.y = tf32f(vals[1]);
            f0.z = tf32f(vals[2]); f0.w = tf32f(vals[3]);
            f1.x = tf32f(vals[4]); f1.y = tf32f(vals[5]);
            f1.z = tf32f(vals[6]); f1.w = tf32f(vals[7]);
            *(float4*)(sm + ES_A0 + e * 36 + c4 * 8) = f0;
            *(float4*)(sm + ES_A0 + e * 36 + c4 * 8 + 4) = f1;
        }

        float acc[3][4][4];
        #pragma unroll
        for (int mt = 0; mt < 3; mt++)
            #pragma unroll
            for (int j = 0; j < 4; j++)
                #pragma unroll
                for (int q = 0; q < 4; q++) acc[mt][j][q] = 0.0f;

        for (int st = 0; st < 40; st++) {
            cp_wait0();
            __syncthreads();
            if (st + 1 < 40) {
                stage_ws_async(g_wsr, SF, st + 1,
                               sm + (((st + 1) & 1) ? ES_W1 : ES_W0), tid);
                cp_commit();
            }
            const float* Wc = sm + ((st & 1) ? ES_W1 : ES_W0);
            const float* As = sm + ((st & 1) ? ES_A1 : ES_A0);
            #pragma unroll
            for (int k8h = 0; k8h < 2; k8h++) {
                int ko = (2 * kh + k8h) * 8;
                unsigned af[3][4];
                #pragma unroll
                for (int mt = 0; mt < 3; mt++) {
                    const float* Ab = As + (mt * 16) * 36;
                    af[mt][0] = __float_as_uint(Ab[g * 36 + ko + t]);
                    af[mt][1] = __float_as_uint(Ab[(g + 8) * 36 + ko + t]);
                    af[mt][2] = __float_as_uint(Ab[g * 36 + ko + t + 4]);
                    af[mt][3] = __float_as_uint(Ab[(g + 8) * 36 + ko + t + 4]);
                }
                #pragma unroll
                for (int j = 0; j < 4; j++) {
                    unsigned b0 = __float_as_uint(
                        Wc[(32 * ng + 8 * j + g) * 36 + ko + t]);
                    unsigned b1 = __float_as_uint(
                        Wc[(32 * ng + 8 * j + g) * 36 + ko + t + 4]);
                    #pragma unroll
                    for (int mt = 0; mt < 3; mt++)
                        mma_tf32(acc[mt][j][0], acc[mt][j][1], acc[mt][j][2],
                                 acc[mt][j][3], af[mt][0], af[mt][1],
                                 af[mt][2], af[mt][3], b0, b1);
                }
            }
            if (st + 1 < 40 && tid < 192) {
                int e = tid >> 2, c4 = tid & 3;
                int cell = 4 * (st + 1) + c4;
                float v = SDv[cell * 49 + e];
                float gg = SDg[cell * 49 + e];
                float vals[8];
                vals[0] = v;
                #pragma unroll
                for (int r = 1; r < 8; r++) { v *= gg; gg *= S_E2; vals[r] = v; }
                float4 f0, f1;
                f0.x = tf32f(vals[0]); f0.y = tf32f(vals[1]);
                f0.z = tf32f(vals[2]); f0.w = tf32f(vals[3]);
                f1.x = tf32f(vals[4]); f1.y = tf32f(vals[5]);
                f1.z = tf32f(vals[6]); f1.w = tf32f(vals[7]);
                float* An = sm + (((st + 1) & 1) ? ES_A1 : ES_A0);
                *(float4*)(An + e * 36 + c4 * 8) = f0;
                *(float4*)(An + e * 36 + c4 * 8 + 4) = f1;
            }
        }
        __syncthreads();

        // combine k8-halves: kh==0 writes, kh==1 adds
        float* h = SDv;
        if (kh == 0) {
            #pragma unroll
            for (int mt = 0; mt < 3; mt++)
                #pragma unroll
                for (int j = 0; j < 4; j++) {
                    int col = 32 * ng + 8 * j + 2 * t;
                    int row = mt * 16 + g;
                    *(float2*)(h + row * 128 + col) =
                        make_float2(acc[mt][j][0], acc[mt][j][1]);
                    *(float2*)(h + (row + 8) * 128 + col) =
                        make_float2(acc[mt][j][2], acc[mt][j][3]);
                }
        }
        __syncthreads();
        if (kh == 1) {
            #pragma unroll
            for (int mt = 0; mt < 3; mt++)
                #pragma unroll
                for (int j = 0; j < 4; j++) {
                    int col = 32 * ng + 8 * j + 2 * t;
                    int row = mt * 16 + g;
                    float2* p0 = (float2*)(h + row * 128 + col);
                    float2* p1 = (float2*)(h + (row + 8) * 128 + col);
                    float2 v0 = *p0, v1 = *p1;
                    v0.x += acc[mt][j][0]; v0.y += acc[mt][j][1];
                    v1.x += acc[mt][j][2]; v1.y += acc[mt][j][3];
                    *p0 = v0; *p1 = v1;
                }
        }
        __syncthreads();

        ln_epilogue<48>(h, gs, bs, out, OFF_ES, i * TOPK, wid, lane);
    }
}

// ---------------------------------------------------------------------------
extern "C" void kernel_launch(void* const* d_in, const int* in_sizes, int n_in,
                              void* d_out, int out_size) {
    (void)in_sizes; (void)n_in; (void)out_size;
    const float* X     = (const float*)d_in[0];
    const float* mask  = (const float*)d_in[2];
    const float* amask = (const float*)d_in[3];
    const int*   ridx  = (const int*)d_in[4];
    const int*   clab  = (const int*)d_in[6];
    const float* Wpos  = (const float*)d_in[7];
    const float* bpos  = (const float*)d_in[8];
    const float* We    = (const float*)d_in[9];
    const float* ge    = (const float*)d_in[10];
    const float* be    = (const float*)d_in[11];
    const float* Ws    = (const float*)d_in[12];
    const float* gs    = (const float*)d_in[13];
    const float* bs    = (const float*)d_in[14];
    float* out = (float*)d_out;

    int u_smem = U_TOT * 4;   // 113408
    cudaFuncSetAttribute(feat_kernel,
                         cudaFuncAttributeMaxDynamicSharedMemorySize, u_smem);

    geom_kernel<<<(LRES + 255) / 256, 256>>>(X);
    wcvt_kernel<<<(128 * SF + 255) / 256, 256>>>(Ws, We);
    topk_kernel<<<LRES, 256>>>(X, mask, out);
    feat_kernel<<<512 + LRES, 256, u_smem>>>(X, amask, ridx, clab, Wpos, bpos,
                                             ge, be, gs, bs, out);
}

// round 16
// speedup vs baseline: 1.6853x; 1.3860x over previous
#include <cuda_runtime.h>
#include <cuda_fp16.h>

#define LRES 1024
#define TOPK 48
#define EF   416
#define SF   1280
#define AP   40      // half-pitch for A/W smem tiles

#define OFF_E       0ull
#define OFF_EIDX    6291456ull
#define OFF_ES      6340608ull
#define OFF_EIDXSUB 12632064ull

__device__ float g_coords[LRES * 15];
__device__ int   g_eidx[LRES * TOPK];
__device__ float g_dnb[LRES * TOPK];
__device__ __half g_wsh[128 * SF];   // fp16 W_s
__device__ __half g_weh[128 * EF];   // fp16 W_e

__device__ __forceinline__ unsigned long long u64min_(unsigned long long a,
                                                      unsigned long long b) {
    return a < b ? a : b;
}

__device__ __forceinline__ unsigned long long warpmin_u64(unsigned long long v) {
    #pragma unroll
    for (int o = 16; o; o >>= 1) {
        unsigned long long w = __shfl_xor_sync(0xffffffffu, v, o);
        v = u64min_(v, w);
    }
    return v;
}

__device__ __forceinline__ void cp_commit() {
    asm volatile("cp.async.commit_group;" ::: "memory");
}
__device__ __forceinline__ void cp_wait0() {
    asm volatile("cp.async.wait_group 0;" ::: "memory");
}

__device__ __forceinline__ void mma_f16(float& d0, float& d1, float& d2,
                                        float& d3, unsigned a0, unsigned a1,
                                        unsigned a2, unsigned a3, unsigned b0,
                                        unsigned b1) {
    asm volatile(
        "mma.sync.aligned.m16n8k16.row.col.f32.f16.f16.f32 "
        "{%0,%1,%2,%3}, {%4,%5,%6,%7}, {%8,%9}, {%0,%1,%2,%3};"
        : "+f"(d0), "+f"(d1), "+f"(d2), "+f"(d3)
        : "r"(a0), "r"(a1), "r"(a2), "r"(a3), "r"(b0), "r"(b1));
}

// Chained RBF writing fp16.
template <int NB>
__device__ __forceinline__ void rbf_gen_h(float D, float m,
                                          __half* __restrict__ fr, float SINV,
                                          float D2, float E2c) {
    float s = (D - 2.0f) * SINV;
    float v = __expf(-D2 * s * s);
    float g = __expf(D2 * (2.0f * s - 1.0f));
    float vals[NB];
    vals[0] = v;
    #pragma unroll
    for (int r = 1; r < NB; r++) { v *= g; g *= E2c; vals[r] = v; }
    if (vals[0] < 1e-30f) {
        float sN = s - (float)(NB - 1);
        float v1 = __expf(-D2 * sN * sN);
        float g1 = __expf(-D2 * (2.0f * sN + 1.0f));
        vals[NB - 1] = fmaxf(vals[NB - 1], v1);
        #pragma unroll
        for (int r = NB - 2; r >= 0; r--) {
            v1 *= g1; g1 *= E2c;
            vals[r] = fmaxf(vals[r], v1);
        }
    }
    #pragma unroll
    for (int r = 0; r < NB; r++) fr[r] = __float2half(m * vals[r]);
}

#define E_SINV 0.75f
#define E_D2   1.13777778f
#define E_E2   0.10273980f
#define S_SINV 0.35f
#define S_D2   1.30612245f
#define S_E2   0.07336966f

// stage 128ch x 32feat fp16 tile -> Wsm[ch*AP + f], 16B cp.async
__device__ __forceinline__ void stage_wh_async(const __half* __restrict__ Wsrc,
                                               int stride, int st,
                                               __half* __restrict__ Wsm,
                                               int tid) {
    #pragma unroll
    for (int p = tid; p < 512; p += 256) {
        int ch = p >> 2, fc = p & 3;
        const __half* src = Wsrc + ch * stride + st * 32 + fc * 8;
        unsigned int dst =
            (unsigned int)__cvta_generic_to_shared(Wsm + ch * AP + fc * 8);
        asm volatile("cp.async.ca.shared.global [%0], [%1], 16;"
                     :: "r"(dst), "l"(src) : "memory");
    }
}

// ---------------------------------------------------------------------------
__global__ void wcvt_kernel(const float* __restrict__ Ws,
                            const float* __restrict__ We) {
    int i = blockIdx.x * 256 + threadIdx.x;
    if (i < 128 * SF) g_wsh[i] = __float2half(Ws[i]);
    if (i < 128 * EF) g_weh[i] = __float2half(We[i]);
}

// ---------------------------------------------------------------------------
__global__ void geom_kernel(const float* __restrict__ X) {
    int i = blockIdx.x * blockDim.x + threadIdx.x;
    if (i >= LRES) return;
    const float* xi = X + (size_t)i * 37 * 3;
    float n0 = xi[0],  n1 = xi[1],  n2 = xi[2];
    float a0 = xi[3],  a1 = xi[4],  a2 = xi[5];
    float c0 = xi[6],  c1 = xi[7],  c2 = xi[8];
    float o0 = xi[12], o1 = xi[13], o2 = xi[14];
    float b0 = a0 - n0, b1 = a1 - n1, b2 = a2 - n2;
    float d0 = c0 - a0, d1 = c1 - a1, d2 = c2 - a2;
    float x0 = b1 * d2 - b2 * d1;
    float x1 = b2 * d0 - b0 * d2;
    float x2 = b0 * d1 - b1 * d0;
    float cb0 = -0.58273431f * x0 + 0.56802827f * b0 - 0.54067466f * d0 + a0;
    float cb1 = -0.58273431f * x1 + 0.56802827f * b1 - 0.54067466f * d1 + a1;
    float cb2 = -0.58273431f * x2 + 0.56802827f * b2 - 0.54067466f * d2 + a2;
    float* dst = g_coords + i * 15;
    dst[0] = n0;  dst[1] = n1;  dst[2] = n2;
    dst[3] = a0;  dst[4] = a1;  dst[5] = a2;
    dst[6] = c0;  dst[7] = c1;  dst[8] = c2;
    dst[9] = o0;  dst[10] = o1; dst[11] = o2;
    dst[12] = cb0; dst[13] = cb1; dst[14] = cb2;
}

// ---------------------------------------------------------------------------
__global__ void topk_kernel(const float* __restrict__ X,
                            const float* __restrict__ mask,
                            float* __restrict__ out) {
    __shared__ float dsh[LRES];
    __shared__ unsigned long long keys[LRES];
    __shared__ unsigned long long cmin[32];
    __shared__ float wmaxs[8];
    __shared__ float smDmax;

    int i = blockIdx.x;
    int tid = threadIdx.x;
    int wid = tid >> 5, lane = tid & 31;
    float cax = X[((size_t)i * 37 + 1) * 3 + 0];
    float cay = X[((size_t)i * 37 + 1) * 3 + 1];
    float caz = X[((size_t)i * 37 + 1) * 3 + 2];
    float mi = mask[i];

    float lmax = 0.0f;
    for (int j = tid; j < LRES; j += 256) {
        float dx = cax - X[((size_t)j * 37 + 1) * 3 + 0];
        float dy = cay - X[((size_t)j * 37 + 1) * 3 + 1];
        float dz = caz - X[((size_t)j * 37 + 1) * 3 + 2];
        float s = dx * dx + dy * dy + dz * dz;
        float m2 = mi * mask[j];
        float Dv = m2 * sqrtf(s + 1e-6f);
        dsh[j] = Dv;
        lmax = fmaxf(lmax, Dv);
    }
    for (int off = 16; off; off >>= 1)
        lmax = fmaxf(lmax, __shfl_xor_sync(0xffffffffu, lmax, off));
    if (lane == 0) wmaxs[wid] = lmax;
    __syncthreads();
    if (tid == 0) {
        float m = wmaxs[0];
        #pragma unroll
        for (int w = 1; w < 8; w++) m = fmaxf(m, wmaxs[w]);
        smDmax = m;
    }
    __syncthreads();
    float Dmax = smDmax;

    for (int j = tid; j < LRES; j += 256) {
        float m2 = mi * mask[j];
        float Dadj = dsh[j] + (1.0f - m2) * Dmax;
        keys[j] = (((unsigned long long)__float_as_uint(Dadj)) << 32) |
                  (unsigned int)j;
    }
    __syncthreads();

    #pragma unroll
    for (int q = 0; q < 4; q++) {
        int c = wid * 4 + q;
        unsigned long long v = keys[c * 32 + lane];
        v = warpmin_u64(v);
        if (lane == 0) cmin[c] = v;
    }
    __syncthreads();

    if (wid == 0) {
        for (int sel = 0; sel < TOPK; sel++) {
            unsigned long long v = cmin[lane];
            unsigned long long m = warpmin_u64(v);
            int j = (int)(m & 0xffffffffull);
            if (lane == 0) {
                float dv = __uint_as_float((unsigned int)(m >> 32));
                g_eidx[i * TOPK + sel] = j;
                g_dnb[i * TOPK + sel] = dv;
                out[OFF_EIDX + (size_t)i * TOPK + sel] = (float)j;
                out[OFF_EIDXSUB + (size_t)i * TOPK + sel] = (float)j;
                keys[j] = 0xffffffffffffffffull;
            }
            __syncwarp();
            int c = j >> 5;
            unsigned long long kv = keys[c * 32 + lane];
            kv = warpmin_u64(kv);
            if (lane == 0) cmin[c] = kv;
            __syncwarp();
        }
    }
}

// ---------------------------------------------------------------------------
template <int NROW>
__device__ __forceinline__ void ln_epilogue(const float* __restrict__ h,
                                            const float* __restrict__ gg,
                                            const float* __restrict__ bb,
                                            float* __restrict__ out,
                                            size_t off, int row0, int wid,
                                            int lane) {
    for (int k = wid; k < NROW; k += 8) {
        float v0 = h[k * 128 + lane];
        float v1 = h[k * 128 + lane + 32];
        float v2 = h[k * 128 + lane + 64];
        float v3 = h[k * 128 + lane + 96];
        float s = v0 + v1 + v2 + v3;
        for (int o = 16; o; o >>= 1) s += __shfl_xor_sync(0xffffffffu, s, o);
        float mu = s * (1.0f / 128.0f);
        float d0 = v0 - mu, d1 = v1 - mu, d2 = v2 - mu, d3 = v3 - mu;
        float s2 = d0 * d0 + d1 * d1 + d2 * d2 + d3 * d3;
        for (int o = 16; o; o >>= 1) s2 += __shfl_xor_sync(0xffffffffu, s2, o);
        float inv = rsqrtf(s2 * (1.0f / 128.0f) + 1e-5f);
        size_t base = off + ((size_t)(row0 + k)) * 128;
        out[base + lane]      = gg[lane]      * d0 * inv + bb[lane];
        out[base + lane + 32] = gg[lane + 32] * d1 * inv + bb[lane + 32];
        out[base + lane + 64] = gg[lane + 64] * d2 * inv + bb[lane + 64];
        out[base + lane + 96] = gg[lane + 96] * d3 * inv + bb[lane + 96];
    }
}

// ---------------------------------------------------------------------------
// Fused feature kernel, fp16 mma (m16n8k16).
// Blocks [0,512): E role (2 residues, M=96). Blocks [512,1536): E_s (M=48).
// Byte layout:
//  common: W0 @0 [10240], W1 @10240 [10240]
//  E:  A0 @20480 [7680], A1 @28160 [7680], SD @35840 [9408]; h floats @0
//  Es: A0 @20480 [3840], A1 @24320 [3840], SDv @28160 [31360],
//      SDg @59520 [31360]; h aliases SDv
#define U_BYTES 90880
#define WB0 0
#define WB1 10240
#define EAB0 20480
#define EAB1 28160
#define ESDB 35840
#define SAB0 20480
#define SAB1 24320
#define SDVB 28160
#define SDGB 59520

__global__ void __launch_bounds__(256, 2) feat_kernel(
    const float* __restrict__ X, const float* __restrict__ amask,
    const int* __restrict__ ridx, const int* __restrict__ clab,
    const float* __restrict__ Wpos, const float* __restrict__ bpos,
    const float* __restrict__ ge, const float* __restrict__ be,
    const float* __restrict__ gs, const float* __restrict__ bs,
    float* __restrict__ out) {
    extern __shared__ char smc[];
    __shared__ int jn[96];
    __shared__ float anch[30];

    int tid = threadIdx.x;
    int wid = tid >> 5, lane = tid & 31;
    int g = lane >> 2, t = lane & 3;

    if (blockIdx.x < 512) {
        // ---------------- E role (M=96): warp = (N32-group, M-half) --------
        int bx = blockIdx.x;
        float* SD = (float*)(smc + ESDB);
        int ng = wid & 3, mh = wid >> 2;

        stage_wh_async(g_weh, EF, 0, (__half*)(smc + WB0), tid);
        cp_commit();

        if (tid < 96) {
            int e = tid;
            int r = (e >= 48);
            int ires = 2 * bx + r;
            int j = g_eidx[96 * bx + e];
            int offr = ridx[ires] - ridx[j];
            int ec = (clab[ires] == clab[j]) ? 1 : 0;
            int d = min(max(offr + 32, 0), 64) * ec + (1 - ec) * 65;
            __half* fr = (__half*)(smc + EAB0) + e * AP;
            #pragma unroll
            for (int f = 0; f < 16; f++)
                fr[f] = __float2half(Wpos[f * 66 + d] + bpos[f]);
            rbf_gen_h<16>(g_dnb[96 * bx + e], 1.0f, fr + 16, E_SINV, E_D2,
                          E_E2);
        }

        const signed char pa[24] =
            {0,2,3,4,1,1,1,1,0,0,0,4,4,3,0,2,3,4,2,3,4,2,3,2};
        const signed char pb[24] =
            {0,2,3,4,0,2,3,4,2,3,4,2,3,2,1,1,1,1,0,0,0,4,4,3};
        for (int tt = tid; tt < 96 * 24; tt += 256) {
            int k = tt / 24, p = tt - k * 24;
            int r = (k >= 48);
            int ires = 2 * bx + r;
            int j = g_eidx[96 * bx + k];
            const float* A = g_coords + ires * 15 + (int)pa[p] * 3;
            const float* B = g_coords + j * 15 + (int)pb[p] * 3;
            float dx = A[0] - B[0], dy = A[1] - B[1], dz = A[2] - B[2];
            SD[p * 98 + k] = sqrtf(dx * dx + dy * dy + dz * dz + 1e-6f);
        }

        float acc[3][4][4];
        #pragma unroll
        for (int mt = 0; mt < 3; mt++)
            #pragma unroll
            for (int j = 0; j < 4; j++)
                #pragma unroll
                for (int q = 0; q < 4; q++) acc[mt][j][q] = 0.0f;

        for (int st = 0; st < 13; st++) {
            cp_wait0();
            __syncthreads();
            if (st + 1 < 13) {
                stage_wh_async(g_weh, EF, st + 1,
                               (__half*)(smc + (((st + 1) & 1) ? WB1 : WB0)),
                               tid);
                cp_commit();
            }
            const __half* Wc = (const __half*)(smc + ((st & 1) ? WB1 : WB0));
            const __half* As = (const __half*)(smc + ((st & 1) ? EAB1 : EAB0));
            #pragma unroll
            for (int k16 = 0; k16 < 2; k16++) {
                int ko = k16 * 16;
                unsigned af[3][4];
                #pragma unroll
                for (int mt = 0; mt < 3; mt++) {
                    const __half* Ab = As + ((mh * 3 + mt) * 16) * AP;
                    af[mt][0] = *(const unsigned*)(Ab + g * AP + ko + 2 * t);
                    af[mt][1] =
                        *(const unsigned*)(Ab + (g + 8) * AP + ko + 2 * t);
                    af[mt][2] =
                        *(const unsigned*)(Ab + g * AP + ko + 2 * t + 8);
                    af[mt][3] =
                        *(const unsigned*)(Ab + (g + 8) * AP + ko + 2 * t + 8);
                }
                #pragma unroll
                for (int j = 0; j < 4; j++) {
                    const __half* Wr = Wc + (32 * ng + 8 * j + g) * AP + ko;
                    unsigned b0 = *(const unsigned*)(Wr + 2 * t);
                    unsigned b1 = *(const unsigned*)(Wr + 2 * t + 8);
                    #pragma unroll
                    for (int mt = 0; mt < 3; mt++)
                        mma_f16(acc[mt][j][0], acc[mt][j][1], acc[mt][j][2],
                                acc[mt][j][3], af[mt][0], af[mt][1],
                                af[mt][2], af[mt][3], b0, b1);
                }
            }
            if (st + 1 < 13 && tid < 192) {
                int e = tid >> 1, pp = tid & 1;
                int p = 2 * st + pp;
                float D = SD[p * 98 + e];
                __half* fr = (__half*)(smc + (((st + 1) & 1) ? EAB1 : EAB0)) +
                             e * AP + pp * 16;
                rbf_gen_h<16>(D, 1.0f, fr, E_SINV, E_D2, E_E2);
            }
        }
        __syncthreads();

        float* h = (float*)smc;
        #pragma unroll
        for (int mt = 0; mt < 3; mt++)
            #pragma unroll
            for (int j = 0; j < 4; j++) {
                int col = 32 * ng + 8 * j + 2 * t;
                int row = (mh * 3 + mt) * 16 + g;
                *(float2*)(h + row * 128 + col) =
                    make_float2(acc[mt][j][0], acc[mt][j][1]);
                *(float2*)(h + (row + 8) * 128 + col) =
                    make_float2(acc[mt][j][2], acc[mt][j][3]);
            }
        __syncthreads();

        ln_epilogue<96>(h, ge, be, out, OFF_E, 96 * bx, wid, lane);
    } else {
        // ---------------- E_s role (M=48): warp = (N32-group, k16-half) ----
        int i = blockIdx.x - 512;
        float* SDv = (float*)(smc + SDVB);
        float* SDg = (float*)(smc + SDGB);
        int ng = wid & 3, kh = wid >> 2;

        stage_wh_async(g_wsh, SF, 0, (__half*)(smc + WB0), tid);
        cp_commit();

        if (tid < TOPK) jn[tid] = g_eidx[i * TOPK + tid];
        if (tid >= 64 && tid < 79)
            anch[tid - 64] = g_coords[i * 15 + (tid - 64)];
        __syncthreads();

        #pragma unroll
        for (int it = 0; it < 6; it++) {
            int task = tid + 256 * it;
            int e = task >> 5, s = task & 31;
            int j = jn[e];
            size_t bi = (size_t)j * 37 + 5 + s;
            float x0 = X[bi * 3 + 0], x1 = X[bi * 3 + 1], x2 = X[bi * 3 + 2];
            float m = amask[bi];
            #pragma unroll
            for (int a = 0; a < 5; a++) {
                float dx = anch[a * 3 + 0] - x0;
                float dy = anch[a * 3 + 1] - x1;
                float dz = anch[a * 3 + 2] - x2;
                float D = sqrtf(dx * dx + dy * dy + dz * dz + 1e-6f);
                float sc = (D - 2.0f) * S_SINV;
                float v = m * __expf(-S_D2 * sc * sc);
                float gg = __expf(S_D2 * (2.0f * sc - 1.0f));
                int cell = a * 32 + s;
                SDv[cell * 49 + e] = v;
                SDg[cell * 49 + e] = gg;
            }
        }
        __syncthreads();

        if (tid < 192) {
            int e = tid >> 2, c4 = tid & 3;
            float v = SDv[c4 * 49 + e];
            float gg = SDg[c4 * 49 + e];
            __half* fr = (__half*)(smc + SAB0) + e * AP + c4 * 8;
            float vv = v;
            #pragma unroll
            for (int r = 0; r < 8; r++) {
                fr[r] = __float2half(vv);
                vv *= gg; gg *= S_E2;
            }
        }

        float acc[3][4][4];
        #pragma unroll
        for (int mt = 0; mt < 3; mt++)
            #pragma unroll
            for (int j = 0; j < 4; j++)
                #pragma unroll
                for (int q = 0; q < 4; q++) acc[mt][j][q] = 0.0f;

        for (int st = 0; st < 40; st++) {
            cp_wait0();
            __syncthreads();
            if (st + 1 < 40) {
                stage_wh_async(g_wsh, SF, st + 1,
                               (__half*)(smc + (((st + 1) & 1) ? WB1 : WB0)),
                               tid);
                cp_commit();
            }
            const __half* Wc = (const __half*)(smc + ((st & 1) ? WB1 : WB0));
            const __half* As = (const __half*)(smc + ((st & 1) ? SAB1 : SAB0));
            {
                int ko = kh * 16;
                unsigned af[3][4];
                #pragma unroll
                for (int mt = 0; mt < 3; mt++) {
                    const __half* Ab = As + (mt * 16) * AP;
                    af[mt][0] = *(const unsigned*)(Ab + g * AP + ko + 2 * t);
                    af[mt][1] =
                        *(const unsigned*)(Ab + (g + 8) * AP + ko + 2 * t);
                    af[mt][2] =
                        *(const unsigned*)(Ab + g * AP + ko + 2 * t + 8);
                    af[mt][3] =
                        *(const unsigned*)(Ab + (g + 8) * AP + ko + 2 * t + 8);
                }
                #pragma unroll
                for (int j = 0; j < 4; j++) {
                    const __half* Wr = Wc + (32 * ng + 8 * j + g) * AP + ko;
                    unsigned b0 = *(const unsigned*)(Wr + 2 * t);
                    unsigned b1 = *(const unsigned*)(Wr + 2 * t + 8);
                    #pragma unroll
                    for (int mt = 0; mt < 3; mt++)
                        mma_f16(acc[mt][j][0], acc[mt][j][1], acc[mt][j][2],
                                acc[mt][j][3], af[mt][0], af[mt][1],
                                af[mt][2], af[mt][3], b0, b1);
                }
            }
            if (st + 1 < 40 && tid < 192) {
                int e = tid >> 2, c4 = tid & 3;
                int cell = 4 * (st + 1) + c4;
                float v = SDv[cell * 49 + e];
                float gg = SDg[cell * 49 + e];
                __half* fr =
                    (__half*)(smc + (((st + 1) & 1) ? SAB1 : SAB0)) + e * AP +
                    c4 * 8;
                float vv = v;
                #pragma unroll
                for (int r = 0; r < 8; r++) {
                    fr[r] = __float2half(vv);
                    vv *= gg; gg *= S_E2;
                }
            }
        }
        __syncthreads();

        float* h = SDv;
        if (kh == 0) {
            #pragma unroll
            for (int mt = 0; mt < 3; mt++)
                #pragma unroll
                for (int j = 0; j < 4; j++) {
                    int col = 32 * ng + 8 * j + 2 * t;
                    int row = mt * 16 + g;
                    *(float2*)(h + row * 128 + col) =
                        make_float2(acc[mt][j][0], acc[mt][j][1]);
                    *(float2*)(h + (row + 8) * 128 + col) =
                        make_float2(acc[mt][j][2], acc[mt][j][3]);
                }
        }
        __syncthreads();
        if (kh == 1) {
            #pragma unroll
            for (int mt = 0; mt < 3; mt++)
                #pragma unroll
                for (int j = 0; j < 4; j++) {
                    int col = 32 * ng + 8 * j + 2 * t;
                    int row = mt * 16 + g;
                    float2* p0 = (float2*)(h + row * 128 + col);
                    float2* p1 = (float2*)(h + (row + 8) * 128 + col);
                    float2 v0 = *p0, v1 = *p1;
                    v0.x += acc[mt][j][0]; v0.y += acc[mt][j][1];
                    v1.x += acc[mt][j][2]; v1.y += acc[mt][j][3];
                    *p0 = v0; *p1 = v1;
                }
        }
        __syncthreads();

        ln_epilogue<48>(h, gs, bs, out, OFF_ES, i * TOPK, wid, lane);
    }
}

// ---------------------------------------------------------------------------
extern "C" void kernel_launch(void* const* d_in, const int* in_sizes, int n_in,
                              void* d_out, int out_size) {
    (void)in_sizes; (void)n_in; (void)out_size;
    const float* X     = (const float*)d_in[0];
    const float* mask  = (const float*)d_in[2];
    const float* amask = (const float*)d_in[3];
    const int*   ridx  = (const int*)d_in[4];
    const int*   clab  = (const int*)d_in[6];
    const float* Wpos  = (const float*)d_in[7];
    const float* bpos  = (const float*)d_in[8];
    const float* We    = (const float*)d_in[9];
    const float* ge    = (const float*)d_in[10];
    const float* be    = (const float*)d_in[11];
    const float* Ws    = (const float*)d_in[12];
    const float* gs    = (const float*)d_in[13];
    const float* bs    = (const float*)d_in[14];
    float* out = (float*)d_out;

    cudaFuncSetAttribute(feat_kernel,
                         cudaFuncAttributeMaxDynamicSharedMemorySize, U_BYTES);

    geom_kernel<<<(LRES + 255) / 256, 256>>>(X);
    wcvt_kernel<<<(128 * SF + 255) / 256, 256>>>(Ws, We);
    topk_kernel<<<LRES, 256>>>(X, mask, out);
    feat_kernel<<<512 + LRES, 256, U_BYTES>>>(X, amask, ridx, clab, Wpos, bpos,
                                              ge, be, gs, bs, out);
}

// round 17
// speedup vs baseline: 1.7880x; 1.0610x over previous
#include <cuda_runtime.h>
#include <cuda_fp16.h>

#define LRES 1024
#define TOPK 48
#define EF   416
#define SF   1280
#define AP   40      // half-pitch for A/W smem tiles

#define OFF_E       0ull
#define OFF_EIDX    6291456ull
#define OFF_ES      6340608ull
#define OFF_EIDXSUB 12632064ull

__device__ float g_coords[LRES * 15];
__device__ int   g_eidx[LRES * TOPK];
__device__ float g_dnb[LRES * TOPK];
__device__ __half g_wsh[128 * SF];   // fp16 W_s
__device__ __half g_weh[128 * EF];   // fp16 W_e

__device__ __forceinline__ unsigned long long u64min_(unsigned long long a,
                                                      unsigned long long b) {
    return a < b ? a : b;
}

__device__ __forceinline__ unsigned long long warpmin_u64(unsigned long long v) {
    #pragma unroll
    for (int o = 16; o; o >>= 1) {
        unsigned long long w = __shfl_xor_sync(0xffffffffu, v, o);
        v = u64min_(v, w);
    }
    return v;
}

__device__ __forceinline__ void cp_commit() {
    asm volatile("cp.async.commit_group;" ::: "memory");
}
__device__ __forceinline__ void cp_wait0() {
    asm volatile("cp.async.wait_group 0;" ::: "memory");
}

__device__ __forceinline__ void mma_f16(float& d0, float& d1, float& d2,
                                        float& d3, unsigned a0, unsigned a1,
                                        unsigned a2, unsigned a3, unsigned b0,
                                        unsigned b1) {
    asm volatile(
        "mma.sync.aligned.m16n8k16.row.col.f32.f16.f16.f32 "
        "{%0,%1,%2,%3}, {%4,%5,%6,%7}, {%8,%9}, {%0,%1,%2,%3};"
        : "+f"(d0), "+f"(d1), "+f"(d2), "+f"(d3)
        : "r"(a0), "r"(a1), "r"(a2), "r"(a3), "r"(b0), "r"(b1));
}

__device__ __forceinline__ void ldsm_x4(unsigned& r0, unsigned& r1,
                                        unsigned& r2, unsigned& r3,
                                        unsigned addr) {
    asm volatile(
        "ldmatrix.sync.aligned.m8n8.x4.shared.b16 {%0,%1,%2,%3}, [%4];"
        : "=r"(r0), "=r"(r1), "=r"(r2), "=r"(r3) : "r"(addr));
}

// Chained RBF writing fp16.
template <int NB>
__device__ __forceinline__ void rbf_gen_h(float D, float m,
                                          __half* __restrict__ fr, float SINV,
                                          float D2, float E2c) {
    float s = (D - 2.0f) * SINV;
    float v = __expf(-D2 * s * s);
    float g = __expf(D2 * (2.0f * s - 1.0f));
    float vals[NB];
    vals[0] = v;
    #pragma unroll
    for (int r = 1; r < NB; r++) { v *= g; g *= E2c; vals[r] = v; }
    if (vals[0] < 1e-30f) {
        float sN = s - (float)(NB - 1);
        float v1 = __expf(-D2 * sN * sN);
        float g1 = __expf(-D2 * (2.0f * sN + 1.0f));
        vals[NB - 1] = fmaxf(vals[NB - 1], v1);
        #pragma unroll
        for (int r = NB - 2; r >= 0; r--) {
            v1 *= g1; g1 *= E2c;
            vals[r] = fmaxf(vals[r], v1);
        }
    }
    #pragma unroll
    for (int r = 0; r < NB; r++) fr[r] = __float2half(m * vals[r]);
}

#define E_SINV 0.75f
#define E_D2   1.13777778f
#define E_E2   0.10273980f
#define S_SINV 0.35f
#define S_D2   1.30612245f
#define S_E2   0.07336966f

// stage 128ch x 32feat fp16 tile -> Wsm[ch*AP + f], 16B cp.async
__device__ __forceinline__ void stage_wh_async(const __half* __restrict__ Wsrc,
                                               int stride, int st,
                                               __half* __restrict__ Wsm,
                                               int tid) {
    #pragma unroll
    for (int p = tid; p < 512; p += 256) {
        int ch = p >> 2, fc = p & 3;
        const __half* src = Wsrc + ch * stride + st * 32 + fc * 8;
        unsigned int dst =
            (unsigned int)__cvta_generic_to_shared(Wsm + ch * AP + fc * 8);
        asm volatile("cp.async.ca.shared.global [%0], [%1], 16;"
                     :: "r"(dst), "l"(src) : "memory");
    }
}

// ---------------------------------------------------------------------------
__global__ void wcvt_kernel(const float* __restrict__ Ws,
                            const float* __restrict__ We) {
    int i = blockIdx.x * 256 + threadIdx.x;
    if (i < 128 * SF) g_wsh[i] = __float2half(Ws[i]);
    if (i < 128 * EF) g_weh[i] = __float2half(We[i]);
}

// ---------------------------------------------------------------------------
__global__ void geom_kernel(const float* __restrict__ X) {
    int i = blockIdx.x * blockDim.x + threadIdx.x;
    if (i >= LRES) return;
    const float* xi = X + (size_t)i * 37 * 3;
    float n0 = xi[0],  n1 = xi[1],  n2 = xi[2];
    float a0 = xi[3],  a1 = xi[4],  a2 = xi[5];
    float c0 = xi[6],  c1 = xi[7],  c2 = xi[8];
    float o0 = xi[12], o1 = xi[13], o2 = xi[14];
    float b0 = a0 - n0, b1 = a1 - n1, b2 = a2 - n2;
    float d0 = c0 - a0, d1 = c1 - a1, d2 = c2 - a2;
    float x0 = b1 * d2 - b2 * d1;
    float x1 = b2 * d0 - b0 * d2;
    float x2 = b0 * d1 - b1 * d0;
    float cb0 = -0.58273431f * x0 + 0.56802827f * b0 - 0.54067466f * d0 + a0;
    float cb1 = -0.58273431f * x1 + 0.56802827f * b1 - 0.54067466f * d1 + a1;
    float cb2 = -0.58273431f * x2 + 0.56802827f * b2 - 0.54067466f * d2 + a2;
    float* dst = g_coords + i * 15;
    dst[0] = n0;  dst[1] = n1;  dst[2] = n2;
    dst[3] = a0;  dst[4] = a1;  dst[5] = a2;
    dst[6] = c0;  dst[7] = c1;  dst[8] = c2;
    dst[9] = o0;  dst[10] = o1; dst[11] = o2;
    dst[12] = cb0; dst[13] = cb1; dst[14] = cb2;
}

// ---------------------------------------------------------------------------
__global__ void topk_kernel(const float* __restrict__ X,
                            const float* __restrict__ mask,
                            float* __restrict__ out) {
    __shared__ float dsh[LRES];
    __shared__ unsigned long long keys[LRES];
    __shared__ unsigned long long cmin[32];
    __shared__ float wmaxs[8];
    __shared__ float smDmax;

    int i = blockIdx.x;
    int tid = threadIdx.x;
    int wid = tid >> 5, lane = tid & 31;
    float cax = X[((size_t)i * 37 + 1) * 3 + 0];
    float cay = X[((size_t)i * 37 + 1) * 3 + 1];
    float caz = X[((size_t)i * 37 + 1) * 3 + 2];
    float mi = mask[i];

    float lmax = 0.0f;
    for (int j = tid; j < LRES; j += 256) {
        float dx = cax - X[((size_t)j * 37 + 1) * 3 + 0];
        float dy = cay - X[((size_t)j * 37 + 1) * 3 + 1];
        float dz = caz - X[((size_t)j * 37 + 1) * 3 + 2];
        float s = dx * dx + dy * dy + dz * dz;
        float m2 = mi * mask[j];
        float Dv = m2 * sqrtf(s + 1e-6f);
        dsh[j] = Dv;
        lmax = fmaxf(lmax, Dv);
    }
    for (int off = 16; off; off >>= 1)
        lmax = fmaxf(lmax, __shfl_xor_sync(0xffffffffu, lmax, off));
    if (lane == 0) wmaxs[wid] = lmax;
    __syncthreads();
    if (tid == 0) {
        float m = wmaxs[0];
        #pragma unroll
        for (int w = 1; w < 8; w++) m = fmaxf(m, wmaxs[w]);
        smDmax = m;
    }
    __syncthreads();
    float Dmax = smDmax;

    for (int j = tid; j < LRES; j += 256) {
        float m2 = mi * mask[j];
        float Dadj = dsh[j] + (1.0f - m2) * Dmax;
        keys[j] = (((unsigned long long)__float_as_uint(Dadj)) << 32) |
                  (unsigned int)j;
    }
    __syncthreads();

    #pragma unroll
    for (int q = 0; q < 4; q++) {
        int c = wid * 4 + q;
        unsigned long long v = keys[c * 32 + lane];
        v = warpmin_u64(v);
        if (lane == 0) cmin[c] = v;
    }
    __syncthreads();

    if (wid == 0) {
        for (int sel = 0; sel < TOPK; sel++) {
            unsigned long long v = cmin[lane];
            unsigned long long m = warpmin_u64(v);
            int j = (int)(m & 0xffffffffull);
            if (lane == 0) {
                float dv = __uint_as_float((unsigned int)(m >> 32));
                g_eidx[i * TOPK + sel] = j;
                g_dnb[i * TOPK + sel] = dv;
                out[OFF_EIDX + (size_t)i * TOPK + sel] = (float)j;
                out[OFF_EIDXSUB + (size_t)i * TOPK + sel] = (float)j;
                keys[j] = 0xffffffffffffffffull;
            }
            __syncwarp();
            int c = j >> 5;
            unsigned long long kv = keys[c * 32 + lane];
            kv = warpmin_u64(kv);
            if (lane == 0) cmin[c] = kv;
            __syncwarp();
        }
    }
}

// ---------------------------------------------------------------------------
template <int NROW>
__device__ __forceinline__ void ln_epilogue(const float* __restrict__ h,
                                            const float* __restrict__ gg,
                                            const float* __restrict__ bb,
                                            float* __restrict__ out,
                                            size_t off, int row0, int wid,
                                            int lane) {
    for (int k = wid; k < NROW; k += 8) {
        float v0 = h[k * 128 + lane];
        float v1 = h[k * 128 + lane + 32];
        float v2 = h[k * 128 + lane + 64];
        float v3 = h[k * 128 + lane + 96];
        float s = v0 + v1 + v2 + v3;
        for (int o = 16; o; o >>= 1) s += __shfl_xor_sync(0xffffffffu, s, o);
        float mu = s * (1.0f / 128.0f);
        float d0 = v0 - mu, d1 = v1 - mu, d2 = v2 - mu, d3 = v3 - mu;
        float s2 = d0 * d0 + d1 * d1 + d2 * d2 + d3 * d3;
        for (int o = 16; o; o >>= 1) s2 += __shfl_xor_sync(0xffffffffu, s2, o);
        float inv = rsqrtf(s2 * (1.0f / 128.0f) + 1e-5f);
        size_t base = off + ((size_t)(row0 + k)) * 128;
        out[base + lane]      = gg[lane]      * d0 * inv + bb[lane];
        out[base + lane + 32] = gg[lane + 32] * d1 * inv + bb[lane + 32];
        out[base + lane + 64] = gg[lane + 64] * d2 * inv + bb[lane + 64];
        out[base + lane + 96] = gg[lane + 96] * d3 * inv + bb[lane + 96];
    }
}

// ---------------------------------------------------------------------------
// Fused feature kernel, fp16 mma + ldmatrix fragment loads.
// Blocks [0,512): E role (2 residues, M=96). Blocks [512,1536): E_s (M=48).
#define U_BYTES 90880
#define WB0 0
#define WB1 10240
#define EAB0 20480
#define EAB1 28160
#define ESDB 35840
#define SAB0 20480
#define SAB1 24320
#define SDVB 28160
#define SDGB 59520

__global__ void __launch_bounds__(256, 2) feat_kernel(
    const float* __restrict__ X, const float* __restrict__ amask,
    const int* __restrict__ ridx, const int* __restrict__ clab,
    const float* __restrict__ Wpos, const float* __restrict__ bpos,
    const float* __restrict__ ge, const float* __restrict__ be,
    const float* __restrict__ gs, const float* __restrict__ bs,
    float* __restrict__ out) {
    extern __shared__ char smc[];
    __shared__ int jn[96];
    __shared__ float anch[30];

    int tid = threadIdx.x;
    int wid = tid >> 5, lane = tid & 31;
    int g = lane >> 2, t = lane & 3;
    unsigned smBase = (unsigned)__cvta_generic_to_shared(smc);

    if (blockIdx.x < 512) {
        // ---------------- E role (M=96): warp = (N32-group, M-half) --------
        int bx = blockIdx.x;
        float* SD = (float*)(smc + ESDB);
        int ng = wid & 3, mh = wid >> 2;

        stage_wh_async(g_weh, EF, 0, (__half*)(smc + WB0), tid);
        cp_commit();

        if (tid < 96) {
            int e = tid;
            int r = (e >= 48);
            int ires = 2 * bx + r;
            int j = g_eidx[96 * bx + e];
            int offr = ridx[ires] - ridx[j];
            int ec = (clab[ires] == clab[j]) ? 1 : 0;
            int d = min(max(offr + 32, 0), 64) * ec + (1 - ec) * 65;
            __half* fr = (__half*)(smc + EAB0) + e * AP;
            #pragma unroll
            for (int f = 0; f < 16; f++)
                fr[f] = __float2half(Wpos[f * 66 + d] + bpos[f]);
            rbf_gen_h<16>(g_dnb[96 * bx + e], 1.0f, fr + 16, E_SINV, E_D2,
                          E_E2);
        }

        const signed char pa[24] =
            {0,2,3,4,1,1,1,1,0,0,0,4,4,3,0,2,3,4,2,3,4,2,3,2};
        const signed char pb[24] =
            {0,2,3,4,0,2,3,4,2,3,4,2,3,2,1,1,1,1,0,0,0,4,4,3};
        for (int tt = tid; tt < 96 * 24; tt += 256) {
            int k = tt / 24, p = tt - k * 24;
            int r = (k >= 48);
            int ires = 2 * bx + r;
            int j = g_eidx[96 * bx + k];
            const float* A = g_coords + ires * 15 + (int)pa[p] * 3;
            const float* B = g_coords + j * 15 + (int)pb[p] * 3;
            float dx = A[0] - B[0], dy = A[1] - B[1], dz = A[2] - B[2];
            SD[p * 98 + k] = sqrtf(dx * dx + dy * dy + dz * dz + 1e-6f);
        }

        // ldmatrix addresses (ko=0, buffer 0)
        unsigned aAddr[3], bAddr[2];
        {
            int rowA = (lane & 15), colA = (lane >> 4) * 8;
            #pragma unroll
            for (int mt = 0; mt < 3; mt++)
                aAddr[mt] = smBase + EAB0 +
                            (((mh * 3 + mt) * 16 + rowA) * AP + colA) * 2;
            #pragma unroll
            for (int jp = 0; jp < 2; jp++) {
                int jj = 2 * jp + (lane >> 4);
                int col = ((lane >> 3) & 1) * 8;
                int row = 32 * ng + 8 * jj + (lane & 7);
                bAddr[jp] = smBase + WB0 + (row * AP + col) * 2;
            }
        }

        float acc[3][4][4];
        #pragma unroll
        for (int mt = 0; mt < 3; mt++)
            #pragma unroll
            for (int j = 0; j < 4; j++)
                #pragma unroll
                for (int q = 0; q < 4; q++) acc[mt][j][q] = 0.0f;

        for (int st = 0; st < 13; st++) {
            cp_wait0();
            __syncthreads();
            if (st + 1 < 13) {
                stage_wh_async(g_weh, EF, st + 1,
                               (__half*)(smc + (((st + 1) & 1) ? WB1 : WB0)),
                               tid);
                cp_commit();
            }
            unsigned wOff = (st & 1) ? (WB1 - WB0) : 0;
            unsigned aOff = (st & 1) ? (EAB1 - EAB0) : 0;
            #pragma unroll
            for (int k16 = 0; k16 < 2; k16++) {
                unsigned kB = k16 * 32;
                unsigned af[3][4];
                #pragma unroll
                for (int mt = 0; mt < 3; mt++)
                    ldsm_x4(af[mt][0], af[mt][1], af[mt][2], af[mt][3],
                            aAddr[mt] + aOff + kB);
                #pragma unroll
                for (int jp = 0; jp < 2; jp++) {
                    unsigned b00, b01, b10, b11;
                    ldsm_x4(b00, b01, b10, b11, bAddr[jp] + wOff + kB);
                    #pragma unroll
                    for (int mt = 0; mt < 3; mt++) {
                        mma_f16(acc[mt][2 * jp][0], acc[mt][2 * jp][1],
                                acc[mt][2 * jp][2], acc[mt][2 * jp][3],
                                af[mt][0], af[mt][1], af[mt][2], af[mt][3],
                                b00, b01);
                        mma_f16(acc[mt][2 * jp + 1][0], acc[mt][2 * jp + 1][1],
                                acc[mt][2 * jp + 1][2], acc[mt][2 * jp + 1][3],
                                af[mt][0], af[mt][1], af[mt][2], af[mt][3],
                                b10, b11);
                    }
                }
            }
            if (st + 1 < 13 && tid < 192) {
                int e = tid >> 1, pp = tid & 1;
                int p = 2 * st + pp;
                float D = SD[p * 98 + e];
                __half* fr = (__half*)(smc + (((st + 1) & 1) ? EAB1 : EAB0)) +
                             e * AP + pp * 16;
                rbf_gen_h<16>(D, 1.0f, fr, E_SINV, E_D2, E_E2);
            }
        }
        __syncthreads();

        float* h = (float*)smc;
        #pragma unroll
        for (int mt = 0; mt < 3; mt++)
            #pragma unroll
            for (int j = 0; j < 4; j++) {
                int col = 32 * ng + 8 * j + 2 * t;
                int row = (mh * 3 + mt) * 16 + g;
                *(float2*)(h + row * 128 + col) =
                    make_float2(acc[mt][j][0], acc[mt][j][1]);
                *(float2*)(h + (row + 8) * 128 + col) =
                    make_float2(acc[mt][j][2], acc[mt][j][3]);
            }
        __syncthreads();

        ln_epilogue<96>(h, ge, be, out, OFF_E, 96 * bx, wid, lane);
    } else {
        // ---------------- E_s role (M=48): warp = (N32-group, k16-half) ----
        int i = blockIdx.x - 512;
        float* SDv = (float*)(smc + SDVB);
        float* SDg = (float*)(smc + SDGB);
        int ng = wid & 3, kh = wid >> 2;

        stage_wh_async(g_wsh, SF, 0, (__half*)(smc + WB0), tid);
        cp_commit();

        if (tid < TOPK) jn[tid] = g_eidx[i * TOPK + tid];
        if (tid >= 64 && tid < 79)
            anch[tid - 64] = g_coords[i * 15 + (tid - 64)];
        __syncthreads();

        #pragma unroll
        for (int it = 0; it < 6; it++) {
            int task = tid + 256 * it;
            int e = task >> 5, s = task & 31;
            int j = jn[e];
            size_t bi = (size_t)j * 37 + 5 + s;
            float x0 = X[bi * 3 + 0], x1 = X[bi * 3 + 1], x2 = X[bi * 3 + 2];
            float m = amask[bi];
            #pragma unroll
            for (int a = 0; a < 5; a++) {
                float dx = anch[a * 3 + 0] - x0;
                float dy = anch[a * 3 + 1] - x1;
                float dz = anch[a * 3 + 2] - x2;
                float D = sqrtf(dx * dx + dy * dy + dz * dz + 1e-6f);
                float sc = (D - 2.0f) * S_SINV;
                float v = m * __expf(-S_D2 * sc * sc);
                float gg = __expf(S_D2 * (2.0f * sc - 1.0f));
                int cell = a * 32 + s;
                SDv[cell * 49 + e] = v;
                SDg[cell * 49 + e] = gg;
            }
        }
        __syncthreads();

        if (tid < 192) {
            int e = tid >> 2, c4 = tid & 3;
            float v = SDv[c4 * 49 + e];
            float gg = SDg[c4 * 49 + e];
            __half* fr = (__half*)(smc + SAB0) + e * AP + c4 * 8;
            float vv = v;
            #pragma unroll
            for (int r = 0; r < 8; r++) {
                fr[r] = __float2half(vv);
                vv *= gg; gg *= S_E2;
            }
        }

        unsigned aAddr[3], bAddr[2];
        {
            int rowA = (lane & 15), colA = kh * 16 + (lane >> 4) * 8;
            #pragma unroll
            for (int mt = 0; mt < 3; mt++)
                aAddr[mt] =
                    smBase + SAB0 + ((mt * 16 + rowA) * AP + colA) * 2;
            #pragma unroll
            for (int jp = 0; jp < 2; jp++) {
                int jj = 2 * jp + (lane >> 4);
                int col = kh * 16 + ((lane >> 3) & 1) * 8;
                int row = 32 * ng + 8 * jj + (lane & 7);
                bAddr[jp] = smBase + WB0 + (row * AP + col) * 2;
            }
        }

        float acc[3][4][4];
        #pragma unroll
        for (int mt = 0; mt < 3; mt++)
            #pragma unroll
            for (int j = 0; j < 4; j++)
                #pragma unroll
                for (int q = 0; q < 4; q++) acc[mt][j][q] = 0.0f;

        for (int st = 0; st < 40; st++) {
            cp_wait0();
            __syncthreads();
            if (st + 1 < 40) {
                stage_wh_async(g_wsh, SF, st + 1,
                               (__half*)(smc + (((st + 1) & 1) ? WB1 : WB0)),
                               tid);
                cp_commit();
            }
            unsigned wOff = (st & 1) ? (WB1 - WB0) : 0;
            unsigned aOff = (st & 1) ? (SAB1 - SAB0) : 0;
            {
                unsigned af[3][4];
                #pragma unroll
                for (int mt = 0; mt < 3; mt++)
                    ldsm_x4(af[mt][0], af[mt][1], af[mt][2], af[mt][3],
                            aAddr[mt] + aOff);
                #pragma unroll
                for (int jp = 0; jp < 2; jp++) {
                    unsigned b00, b01, b10, b11;
                    ldsm_x4(b00, b01, b10, b11, bAddr[jp] + wOff);
                    #pragma unroll
                    for (int mt = 0; mt < 3; mt++) {
                        mma_f16(acc[mt][2 * jp][0], acc[mt][2 * jp][1],
                                acc[mt][2 * jp][2], acc[mt][2 * jp][3],
                                af[mt][0], af[mt][1], af[mt][2], af[mt][3],
                                b00, b01);
                        mma_f16(acc[mt][2 * jp + 1][0], acc[mt][2 * jp + 1][1],
                                acc[mt][2 * jp + 1][2], acc[mt][2 * jp + 1][3],
                                af[mt][0], af[mt][1], af[mt][2], af[mt][3],
                                b10, b11);
                    }
                }
            }
            if (st + 1 < 40 && tid < 192) {
                int e = tid >> 2, c4 = tid & 3;
                int cell = 4 * (st + 1) + c4;
                float v = SDv[cell * 49 + e];
                float gg = SDg[cell * 49 + e];
                __half* fr =
                    (__half*)(smc + (((st + 1) & 1) ? SAB1 : SAB0)) + e * AP +
                    c4 * 8;
                float vv = v;
                #pragma unroll
                for (int r = 0; r < 8; r++) {
                    fr[r] = __float2half(vv);
                    vv *= gg; gg *= S_E2;
                }
            }
        }
        __syncthreads();

        float* h = SDv;
        if (kh == 0) {
            #pragma unroll
            for (int mt = 0; mt < 3; mt++)
                #pragma unroll
                for (int j = 0; j < 4; j++) {
                    int col = 32 * ng + 8 * j + 2 * t;
                    int row = mt * 16 + g;
                    *(float2*)(h + row * 128 + col) =
                        make_float2(acc[mt][j][0], acc[mt][j][1]);
                    *(float2*)(h + (row + 8) * 128 + col) =
                        make_float2(acc[mt][j][2], acc[mt][j][3]);
                }
        }
        __syncthreads();
        if (kh == 1) {
            #pragma unroll
            for (int mt = 0; mt < 3; mt++)
                #pragma unroll
                for (int j = 0; j < 4; j++) {
                    int col = 32 * ng + 8 * j + 2 * t;
                    int row = mt * 16 + g;
                    float2* p0 = (float2*)(h + row * 128 + col);
                    float2* p1 = (float2*)(h + (row + 8) * 128 + col);
                    float2 v0 = *p0, v1 = *p1;
                    v0.x += acc[mt][j][0]; v0.y += acc[mt][j][1];
                    v1.x += acc[mt][j][2]; v1.y += acc[mt][j][3];
                    *p0 = v0; *p1 = v1;
                }
        }
        __syncthreads();

        ln_epilogue<48>(h, gs, bs, out, OFF_ES, i * TOPK, wid, lane);
    }
}

// ---------------------------------------------------------------------------
extern "C" void kernel_launch(void* const* d_in, const int* in_sizes, int n_in,
                              void* d_out, int out_size) {
    (void)in_sizes; (void)n_in; (void)out_size;
    const float* X     = (const float*)d_in[0];
    const float* mask  = (const float*)d_in[2];
    const float* amask = (const float*)d_in[3];
    const int*   ridx  = (const int*)d_in[4];
    const int*   clab  = (const int*)d_in[6];
    const float* Wpos  = (const float*)d_in[7];
    const float* bpos  = (const float*)d_in[8];
    const float* We    = (const float*)d_in[9];
    const float* ge    = (const float*)d_in[10];
    const float* be    = (const float*)d_in[11];
    const float* Ws    = (const float*)d_in[12];
    const float* gs    = (const float*)d_in[13];
    const float* bs    = (const float*)d_in[14];
    float* out = (float*)d_out;

    cudaFuncSetAttribute(feat_kernel,
                         cudaFuncAttributeMaxDynamicSharedMemorySize, U_BYTES);

    geom_kernel<<<(LRES + 255) / 256, 256>>>(X);
    wcvt_kernel<<<(128 * SF + 255) / 256, 256>>>(Ws, We);
    topk_kernel<<<LRES, 256>>>(X, mask, out);
    feat_kernel<<<512 + LRES, 256, U_BYTES>>>(X, amask, ridx, clab, Wpos, bpos,
                                              ge, be, gs, bs, out);
}